// round 13
// baseline (speedup 1.0000x reference)
#include <cuda_runtime.h>
#include <cuda_fp16.h>
#include <cstdint>

// Problem constants (fixed by the dataset)
#define ND 128
#define NMAX 50000
#define EMAX 640000
#define GMAX 1024
#define RDM 200
#define H1 512
#define H2 256
#define KMLP1 (ND + RDM)   // 328

// ---------------- scratch (device globals; no allocation allowed) ----------
__device__ float g_x0[NMAX * ND];
__device__ float g_agg[NMAX * ND];
__device__ float g_x1[NMAX * ND];
__device__ float g_x2[NMAX * ND];
__device__ float g_pool[GMAX * ND];
__device__ int   g_cnt[GMAX];
__device__ float g_min[GMAX * KMLP1];
__device__ float g_m1[GMAX * H1];
__device__ float g_m2[GMAX * H2];
// prepped conv weights: per matrix 64KB = Wt hi (32KB) + Wt lo (32KB), [n][k] fp16
__device__ uint4 g_wp[4][4096];
// CSR sort scratch. g_deg is zero at the START of every execution:
// zero-initialized at module load; re-zeroed by scatter_kernel at the end of
// each run (after the scan has consumed it). Deterministic across replays.
__device__ int g_deg[NMAX];
__device__ int g_off[NMAX + 1];
__device__ int g_pos[NMAX];
__device__ int g_emeta[EMAX];    // packed per-edge meta (src | f0<<16 | f1<<20 | f2<<24)
__device__ int g_smeta[EMAX];    // meta in dst-sorted order

// ---------------- helpers ----------------------------------------------------
__device__ __forceinline__ unsigned long long pack2(float x, float y) {
    unsigned long long r;
    asm("mov.b64 %0, {%1, %2};" : "=l"(r) : "f"(x), "f"(y));
    return r;
}
__device__ __forceinline__ void unpack2(unsigned long long v, float& x, float& y) {
    asm("mov.b64 {%0, %1}, %2;" : "=f"(x), "=f"(y) : "l"(v));
}
__device__ __forceinline__ void ffma2(unsigned long long& d, unsigned long long a,
                                      unsigned long long b) {
    asm("fma.rn.f32x2 %0, %1, %2, %0;" : "+l"(d) : "l"(a), "l"(b));
}
__device__ __forceinline__ void red_add_v4(float* p, float a, float b, float c, float d) {
    asm volatile("red.global.add.v4.f32 [%0], {%1, %2, %3, %4};"
                 :: "l"(p), "f"(a), "f"(b), "f"(c), "f"(d) : "memory");
}
// hi/lo fp16x2 split of two floats (a=elem0/.x, b=elem1/.y)
__device__ __forceinline__ uint32_t hilo16(float a, float b, uint32_t& lopack) {
    __half2 h2 = __floats2half2_rn(a, b);
    float2 f = __half22float2(h2);
    __half2 l2 = __floats2half2_rn(a - f.x, b - f.y);
    lopack = *reinterpret_cast<uint32_t*>(&l2);
    return *reinterpret_cast<uint32_t*>(&h2);
}
// warp-level fp16 tensor-core mma (baseline PTX, works on plain sm_103)
__device__ __forceinline__ void mma16816(float* c, const uint32_t* a, const uint32_t* b) {
    asm volatile(
        "mma.sync.aligned.m16n8k16.row.col.f32.f16.f16.f32 "
        "{%0,%1,%2,%3}, {%4,%5,%6,%7}, {%8,%9}, {%0,%1,%2,%3};"
        : "+f"(c[0]), "+f"(c[1]), "+f"(c[2]), "+f"(c[3])
        : "r"(a[0]), "r"(a[1]), "r"(a[2]), "r"(a[3]), "r"(b[0]), "r"(b[1]));
}

// ---------------- launch 1: combo — wprep | atom encode | edge prep ----------
// blocks [0,256): W prep; [256, 256+EB): edge prep; rest: atom encode.
// g_deg is guaranteed zero at kernel start (see its declaration comment).
__global__ void prep_combo_kernel(const int* __restrict__ xf,
                                  const float* __restrict__ aemb,
                                  const int* __restrict__ ei,
                                  const int* __restrict__ eaf,
                                  const float* __restrict__ w0, const float* __restrict__ w1,
                                  const float* __restrict__ w2, const float* __restrict__ w3,
                                  float* __restrict__ xout, int N, int E, int EB) {
    if (blockIdx.x < 256) {
        int widx = blockIdx.x >> 6;
        int idx = (blockIdx.x & 63) * 256 + threadIdx.x;   // 0..16383
        const float* W = (widx == 0) ? w0 : (widx == 1) ? w1 : (widx == 2) ? w2 : w3;
        int n = idx >> 7, k = idx & 127;
        float w = W[k * 128 + n];
        __half h = __float2half_rn(w);
        __half l = __float2half_rn(w - __half2float(h));
        __half* base = reinterpret_cast<__half*>(&g_wp[widx][0]);
        base[n * 128 + k] = h;
        base[16384 + n * 128 + k] = l;
        return;
    }
    if ((int)blockIdx.x < 256 + EB) {
        int e = (blockIdx.x - 256) * 256 + threadIdx.x;
        if (e >= E) return;
        int src = ei[e];
        int dst = ei[E + e];
        int f0 = eaf[e * 3 + 0], f1 = eaf[e * 3 + 1], f2 = eaf[e * 3 + 2];
        g_emeta[e] = src | (f0 << 16) | (f1 << 20) | (f2 << 24);
        atomicAdd(&g_deg[dst], 1);
        return;
    }
    // atom encoder (no atomics)
    int warp = ((blockIdx.x - 256 - EB) * blockDim.x + threadIdx.x) >> 5;
    int lane = threadIdx.x & 31;
    if (warp >= N) return;
    int n = warp;
    float4 acc = make_float4(0.f, 0.f, 0.f, 0.f);
#pragma unroll
    for (int f = 0; f < 9; f++) {
        int id = xf[n * 9 + f];
        const float4* row = reinterpret_cast<const float4*>(aemb + ((f << 6) + id) * ND);
        float4 v = row[lane];
        acc.x += v.x; acc.y += v.y; acc.z += v.z; acc.w += v.w;
    }
    reinterpret_cast<float4*>(xout + (size_t)n * ND)[lane] = acc;
}

// ---------------- launch 2: single-block multi-round scan + graph counts -----
__global__ void __launch_bounds__(1024)
scan_single_kernel(const int* __restrict__ batch, int N, int E, int G) {
    __shared__ int sm[1024];
    __shared__ int s_carry;
    const int tid = threadIdx.x;

    // graph counts via binary search on sorted batch (independent work first)
    if (tid < G) {
        int g = tid;
        int lo = 0, hi = N;
        while (lo < hi) { int mid = (lo + hi) >> 1; if (batch[mid] < g) lo = mid + 1; else hi = mid; }
        int lo2 = lo, hi2 = N;
        while (lo2 < hi2) { int mid = (lo2 + hi2) >> 1; if (batch[mid] <= g) lo2 = mid + 1; else hi2 = mid; }
        g_cnt[g] = lo2 - lo;
    }

    if (tid == 0) s_carry = 0;
    __syncthreads();

    const int rounds = (N + 1023) / 1024;
    for (int r = 0; r < rounds; r++) {
        int i = r * 1024 + tid;
        int v = (i < N) ? g_deg[i] : 0;
        sm[tid] = v;
        __syncthreads();
#pragma unroll
        for (int ofs = 1; ofs < 1024; ofs <<= 1) {
            int t = (tid >= ofs) ? sm[tid - ofs] : 0;
            __syncthreads();
            sm[tid] += t;
            __syncthreads();
        }
        int excl = sm[tid] - v + s_carry;
        if (i < N) { g_off[i] = excl; g_pos[i] = excl; }
        __syncthreads();            // all carry reads done
        if (tid == 1023) s_carry += sm[1023];
        __syncthreads();
    }
    if (tid == 0) g_off[N] = E;
}

// ---------------- launch 3: scatter meta into dst-sorted order ---------------
// Also re-zeros g_deg for the next execution (deg is dead after the scan).
__global__ void scatter_kernel(const int* __restrict__ ei, int E, int N) {
    int e = blockIdx.x * blockDim.x + threadIdx.x;
    if (e < N) g_deg[e] = 0;
    if (e >= E) return;
    int dst = ei[E + e];
    int p = atomicAdd(&g_pos[dst], 1);
    g_smeta[p] = g_emeta[e];
}

// ---------------- launch 4 (profiled): gather-aggregate ----------------------
// out[n] = x[n] + sum relu(x[src]+bond); 4x unroll batches the x[src] loads.
__global__ void __launch_bounds__(256)
agg_gather_kernel(const float* __restrict__ xin, const float* __restrict__ bemb,
                  float* __restrict__ out, int N) {
    int wid = threadIdx.x >> 5, lane = threadIdx.x & 31;
    int n = blockIdx.x * 8 + wid;
    if (n >= N) return;
    int s = g_off[n], e_end = g_off[n + 1];
    float4 acc = reinterpret_cast<const float4*>(xin + (size_t)n * ND)[lane];
    for (int base = s; base < e_end; base += 32) {
        int cnt = min(32, e_end - base);
        int mb = (lane < cnt) ? g_smeta[base + lane] : 0;
        int i = 0;
#define ACC_EDGE(m, xs)                                                                       \
        {                                                                                     \
            float4 b0 = __ldg(reinterpret_cast<const float4*>(bemb + (((m) >> 16) & 15) * ND) + lane); \
            float4 b1 = __ldg(reinterpret_cast<const float4*>(bemb + (16 + (((m) >> 20) & 15)) * ND) + lane); \
            float4 b2 = __ldg(reinterpret_cast<const float4*>(bemb + (32 + (((m) >> 24) & 15)) * ND) + lane); \
            acc.x += fmaxf((xs).x + b0.x + b1.x + b2.x, 0.f);                                 \
            acc.y += fmaxf((xs).y + b0.y + b1.y + b2.y, 0.f);                                 \
            acc.z += fmaxf((xs).z + b0.z + b1.z + b2.z, 0.f);                                 \
            acc.w += fmaxf((xs).w + b0.w + b1.w + b2.w, 0.f);                                 \
        }
        for (; i + 4 <= cnt; i += 4) {
            int m0 = __shfl_sync(0xFFFFFFFFu, mb, i);
            int m1 = __shfl_sync(0xFFFFFFFFu, mb, i + 1);
            int m2 = __shfl_sync(0xFFFFFFFFu, mb, i + 2);
            int m3 = __shfl_sync(0xFFFFFFFFu, mb, i + 3);
            float4 xs0 = reinterpret_cast<const float4*>(xin + (size_t)(m0 & 0xFFFF) * ND)[lane];
            float4 xs1 = reinterpret_cast<const float4*>(xin + (size_t)(m1 & 0xFFFF) * ND)[lane];
            float4 xs2 = reinterpret_cast<const float4*>(xin + (size_t)(m2 & 0xFFFF) * ND)[lane];
            float4 xs3 = reinterpret_cast<const float4*>(xin + (size_t)(m3 & 0xFFFF) * ND)[lane];
            ACC_EDGE(m0, xs0)
            ACC_EDGE(m1, xs1)
            ACC_EDGE(m2, xs2)
            ACC_EDGE(m3, xs3)
        }
        for (; i < cnt; i++) {
            int m = __shfl_sync(0xFFFFFFFFu, mb, i);
            float4 xs = reinterpret_cast<const float4*>(xin + (size_t)(m & 0xFFFF) * ND)[lane];
            ACC_EDGE(m, xs)
        }
#undef ACC_EDGE
    }
    reinterpret_cast<float4*>(out + (size_t)n * ND)[lane] = acc;
}

// ---------------- persistent fused 2-layer tensor-core conv GEMM -------------
// C = relu(A @ W1 + b1) @ W2 + b2; fp16 3-chain (AhiWhi + AloWhi + AhiWlo).
#define SAK 136   // padded fp16 stride (272B rows)
#define TTILE (128 * SAK * 2)      // 34816 B
#define FSM (6 * TTILE)            // Ahi,Alo,W1hi,W1lo,W2hi,W2lo = 208896 B
#define GEMM_GRID 148

__global__ void __launch_bounds__(256, 1)
gemm_fused_kernel(const float* __restrict__ A,
                  const uint4* __restrict__ Wp1, const uint4* __restrict__ Wp2,
                  const float* __restrict__ b1, const float* __restrict__ b2,
                  float* __restrict__ C, int M, int ntiles) {
    extern __shared__ char dsm[];
    __shared__ float s_b1[128];
    __shared__ float s_b2[128];

    char* pAhi  = dsm;
    char* pAlo  = dsm + 1 * TTILE;
    char* pW1hi = dsm + 2 * TTILE;
    char* pW1lo = dsm + 3 * TTILE;
    char* pW2hi = dsm + 4 * TTILE;
    char* pW2lo = dsm + 5 * TTILE;
    const uint32_t* sAhi = (const uint32_t*)pAhi;
    const uint32_t* sAlo = (const uint32_t*)pAlo;

    const int tid = threadIdx.x, wid = tid >> 5, lane = tid & 31;
    const int g = lane >> 2, q = lane & 3;
    const int wm = wid & 3, wn = wid >> 2;

    if (tid < 128) { s_b1[tid] = b1[tid]; s_b2[tid] = b2[tid]; }

    // ---- stage W1, W2 once (hi + lo, 32KB each part) ----
#pragma unroll
    for (int i = 0; i < 8; i++) {
        int u = tid + i * 256;              // 0..2047
        int n = u >> 4, kc = u & 15;
        *(uint4*)(pW1hi + n * (SAK * 2) + kc * 16) = Wp1[u];
        *(uint4*)(pW1lo + n * (SAK * 2) + kc * 16) = Wp1[u + 2048];
        *(uint4*)(pW2hi + n * (SAK * 2) + kc * 16) = Wp2[u];
        *(uint4*)(pW2lo + n * (SAK * 2) + kc * 16) = Wp2[u + 2048];
    }

    const int ra0 = wm * 32 + g;
    const int nb0 = wn * 64 + g;

    for (int t = blockIdx.x; t < ntiles; t += GEMM_GRID) {
        const int brow = t * 128;
        __syncthreads();   // W ready (1st iter) / prior tile's readers done

        // ---- stage A: fp32 -> hi/lo fp16 ----
        {
            int row = tid >> 1;
            int c0 = (tid & 1) * 64;
            bool valid = (brow + row) < M;
            const float4* a4 = (const float4*)(A + (size_t)(brow + row) * 128 + c0);
            char* dAh = pAhi + row * (SAK * 2) + c0 * 2;
            char* dAl = pAlo + row * (SAK * 2) + c0 * 2;
#pragma unroll
            for (int i = 0; i < 8; i++) {
                float4 v0 = make_float4(0.f, 0.f, 0.f, 0.f), v1 = v0;
                if (valid) { v0 = a4[i * 2]; v1 = a4[i * 2 + 1]; }
                uint4 h, l;
                h.x = hilo16(v0.x, v0.y, l.x);
                h.y = hilo16(v0.z, v0.w, l.y);
                h.z = hilo16(v1.x, v1.y, l.z);
                h.w = hilo16(v1.z, v1.w, l.w);
                *(uint4*)(dAh + i * 16) = h;
                *(uint4*)(dAl + i * 16) = l;
            }
        }
        __syncthreads();

        float acc[2][8][4];

        // ================= layer 1 =================
#pragma unroll
        for (int mt = 0; mt < 2; mt++)
#pragma unroll
            for (int nt = 0; nt < 8; nt++)
#pragma unroll
                for (int j = 0; j < 4; j++) acc[mt][nt][j] = 0.f;

        {
            const uint32_t* sWhi = (const uint32_t*)pW1hi;
            const uint32_t* sWlo = (const uint32_t*)pW1lo;
#pragma unroll
            for (int ks = 0; ks < 8; ks++) {
                const int k0 = ks * 16 + q * 2;
                uint32_t ah[2][4], al[2][4];
#pragma unroll
                for (int mt = 0; mt < 2; mt++) {
                    int r = ra0 + mt * 16;
                    int i00 = (r * SAK + k0) >> 1;
                    int i10 = ((r + 8) * SAK + k0) >> 1;
                    ah[mt][0] = sAhi[i00];     ah[mt][1] = sAhi[i10];
                    ah[mt][2] = sAhi[i00 + 4]; ah[mt][3] = sAhi[i10 + 4];
                    al[mt][0] = sAlo[i00];     al[mt][1] = sAlo[i10];
                    al[mt][2] = sAlo[i00 + 4]; al[mt][3] = sAlo[i10 + 4];
                }
#pragma unroll
                for (int nt = 0; nt < 8; nt++) {
                    int n = nb0 + nt * 8;
                    int ib = (n * SAK + k0) >> 1;
                    uint32_t bh[2], bl[2];
                    bh[0] = sWhi[ib]; bh[1] = sWhi[ib + 4];
                    bl[0] = sWlo[ib]; bl[1] = sWlo[ib + 4];
#pragma unroll
                    for (int mt = 0; mt < 2; mt++) {
                        mma16816(acc[mt][nt], ah[mt], bh);
                        mma16816(acc[mt][nt], al[mt], bh);
                        mma16816(acc[mt][nt], ah[mt], bl);
                    }
                }
            }
        }
        __syncthreads();   // everyone done reading A tiles before overwrite

        // ---- h = relu(acc + b1) -> hi/lo fp16 back into A buffers ----
#pragma unroll
        for (int mt = 0; mt < 2; mt++) {
            int r0 = wm * 32 + mt * 16 + g;
#pragma unroll
            for (int nt = 0; nt < 8; nt++) {
                int col = wn * 64 + nt * 8 + q * 2;
                float bx = s_b1[col], by = s_b1[col + 1];
                float x0 = fmaxf(acc[mt][nt][0] + bx, 0.f);
                float y0 = fmaxf(acc[mt][nt][1] + by, 0.f);
                float x1 = fmaxf(acc[mt][nt][2] + bx, 0.f);
                float y1 = fmaxf(acc[mt][nt][3] + by, 0.f);
                uint32_t l0, l1;
                uint32_t h0 = hilo16(x0, y0, l0);
                uint32_t h1 = hilo16(x1, y1, l1);
                uint32_t o0 = (uint32_t)(r0 * SAK + col) * 2u;
                uint32_t o1 = (uint32_t)((r0 + 8) * SAK + col) * 2u;
                *(uint32_t*)(pAhi + o0) = h0;
                *(uint32_t*)(pAlo + o0) = l0;
                *(uint32_t*)(pAhi + o1) = h1;
                *(uint32_t*)(pAlo + o1) = l1;
            }
        }
        __syncthreads();

        // ================= layer 2 =================
#pragma unroll
        for (int mt = 0; mt < 2; mt++)
#pragma unroll
            for (int nt = 0; nt < 8; nt++)
#pragma unroll
                for (int j = 0; j < 4; j++) acc[mt][nt][j] = 0.f;

        {
            const uint32_t* sWhi = (const uint32_t*)pW2hi;
            const uint32_t* sWlo = (const uint32_t*)pW2lo;
#pragma unroll
            for (int ks = 0; ks < 8; ks++) {
                const int k0 = ks * 16 + q * 2;
                uint32_t ah[2][4], al[2][4];
#pragma unroll
                for (int mt = 0; mt < 2; mt++) {
                    int r = ra0 + mt * 16;
                    int i00 = (r * SAK + k0) >> 1;
                    int i10 = ((r + 8) * SAK + k0) >> 1;
                    ah[mt][0] = sAhi[i00];     ah[mt][1] = sAhi[i10];
                    ah[mt][2] = sAhi[i00 + 4]; ah[mt][3] = sAhi[i10 + 4];
                    al[mt][0] = sAlo[i00];     al[mt][1] = sAlo[i10];
                    al[mt][2] = sAlo[i00 + 4]; al[mt][3] = sAlo[i10 + 4];
                }
#pragma unroll
                for (int nt = 0; nt < 8; nt++) {
                    int n = nb0 + nt * 8;
                    int ib = (n * SAK + k0) >> 1;
                    uint32_t bh[2], bl[2];
                    bh[0] = sWhi[ib]; bh[1] = sWhi[ib + 4];
                    bl[0] = sWlo[ib]; bl[1] = sWlo[ib + 4];
#pragma unroll
                    for (int mt = 0; mt < 2; mt++) {
                        mma16816(acc[mt][nt], ah[mt], bh);
                        mma16816(acc[mt][nt], al[mt], bh);
                        mma16816(acc[mt][nt], ah[mt], bl);
                    }
                }
            }
        }

        // ---- epilogue: C = acc + b2 ----
#pragma unroll
        for (int mt = 0; mt < 2; mt++) {
            int r0 = brow + wm * 32 + mt * 16 + g;
#pragma unroll
            for (int nt = 0; nt < 8; nt++) {
                int col = wn * 64 + nt * 8 + q * 2;
                float bx = s_b2[col], by = s_b2[col + 1];
                if (r0 < M) {
                    float2 o; o.x = acc[mt][nt][0] + bx; o.y = acc[mt][nt][1] + by;
                    *(float2*)(C + (size_t)r0 * 128 + col) = o;
                }
                if (r0 + 8 < M) {
                    float2 o; o.x = acc[mt][nt][2] + bx; o.y = acc[mt][nt][3] + by;
                    *(float2*)(C + (size_t)(r0 + 8) * 128 + col) = o;
                }
            }
        }
    }
}

// ---------------- fp32 GEMM (MLP only) --------------------------------------
template <int BM, int BN, int BK, int TM, int TN, bool RELU, int MINB>
__global__ void __launch_bounds__((BM / TM) * (BN / TN), MINB)
gemm_kernel(const float* __restrict__ A,
            const float* __restrict__ W, const float* __restrict__ bias,
            float* __restrict__ C, int M, int K, int Nc) {
    constexpr int THREADS = (BM / TM) * (BN / TN);
    __shared__ float sA[BK][BM + 4];
    __shared__ float sW[BK][BN];

    const int tid = threadIdx.x;
    const int tn = tid % (BN / TN);
    const int tm = tid / (BN / TN);
    const int row0 = tm * TM;
    const int col0 = tn * TN;
    const int brow = blockIdx.x * BM;
    const int bcol = blockIdx.y * BN;

    unsigned long long acc[TM][TN / 2];
#pragma unroll
    for (int i = 0; i < TM; i++)
#pragma unroll
        for (int j = 0; j < TN / 2; j++) acc[i][j] = 0ull;

    for (int k0 = 0; k0 < K; k0 += BK) {
        constexpr int A_LOADS = (BM * BK / 4) / THREADS;
#pragma unroll
        for (int i = 0; i < A_LOADS; i++) {
            int idx = tid + i * THREADS;
            int m = idx / (BK / 4);
            int kq = idx % (BK / 4);
            int grow = brow + m;
            float4 v = make_float4(0.f, 0.f, 0.f, 0.f);
            if (grow < M)
                v = *reinterpret_cast<const float4*>(A + (size_t)grow * K + k0 + kq * 4);
            sA[kq * 4 + 0][m] = v.x;
            sA[kq * 4 + 1][m] = v.y;
            sA[kq * 4 + 2][m] = v.z;
            sA[kq * 4 + 3][m] = v.w;
        }
        constexpr int W_LOADS = (BK * BN / 4) / THREADS;
#pragma unroll
        for (int i = 0; i < W_LOADS; i++) {
            int idx = tid + i * THREADS;
            int kk = idx / (BN / 4);
            int cq = idx % (BN / 4);
            *reinterpret_cast<float4*>(&sW[kk][cq * 4]) =
                *reinterpret_cast<const float4*>(W + (size_t)(k0 + kk) * Nc + bcol + cq * 4);
        }
        __syncthreads();

#pragma unroll
        for (int kk = 0; kk < BK; kk++) {
            float a[TM];
#pragma unroll
            for (int i = 0; i < TM; i += 4) {
                float4 t = *reinterpret_cast<const float4*>(&sA[kk][row0 + i]);
                a[i] = t.x; a[i + 1] = t.y; a[i + 2] = t.z; a[i + 3] = t.w;
            }
            unsigned long long wv[TN / 2];
#pragma unroll
            for (int j = 0; j < TN; j += 4) {
                float4 t = *reinterpret_cast<const float4*>(&sW[kk][col0 + j]);
                wv[j / 2] = pack2(t.x, t.y);
                wv[j / 2 + 1] = pack2(t.z, t.w);
            }
#pragma unroll
            for (int i = 0; i < TM; i++) {
                unsigned long long ad = pack2(a[i], a[i]);
#pragma unroll
                for (int j = 0; j < TN / 2; j++) ffma2(acc[i][j], ad, wv[j]);
            }
        }
        __syncthreads();
    }

    float2 bv[TN / 2];
#pragma unroll
    for (int j = 0; j < TN / 2; j++)
        bv[j] = *reinterpret_cast<const float2*>(bias + bcol + col0 + 2 * j);
#pragma unroll
    for (int i = 0; i < TM; i++) {
        int grow = brow + row0 + i;
        if (grow >= M) continue;
#pragma unroll
        for (int j = 0; j < TN / 2; j++) {
            float x, y;
            unpack2(acc[i][j], x, y);
            x += bv[j].x; y += bv[j].y;
            if (RELU) { x = fmaxf(x, 0.f); y = fmaxf(y, 0.f); }
            float2 o; o.x = x; o.y = y;
            *reinterpret_cast<float2*>(C + (size_t)grow * Nc + bcol + col0 + 2 * j) = o;
        }
    }
}

// ---------------- pooling: sum per graph -------------------------------------
__global__ void pool_sum_kernel(const float* __restrict__ x,
                                const int* __restrict__ batch,
                                float* __restrict__ pool, int N) {
    int warp = (blockIdx.x * blockDim.x + threadIdx.x) >> 5;
    int lane = threadIdx.x & 31;
    if (warp >= N) return;
    int n = warp;
    int g = batch[n];
    float4 v = reinterpret_cast<const float4*>(x + (size_t)n * ND)[lane];
    float* p = pool + (size_t)g * ND + lane * 4;
    red_add_v4(p, v.x, v.y, v.z, v.w);
}

// ---------------- concat: pooled mean + rdkit --------------------------------
__global__ void concat_kernel(const float* __restrict__ pool,
                              const float* __restrict__ rdkit,
                              float* __restrict__ out, int G) {
    int idx = blockIdx.x * blockDim.x + threadIdx.x;
    int total = G * KMLP1;
    if (idx >= total) return;
    int g = idx / KMLP1;
    int c = idx - g * KMLP1;
    float v;
    if (c < ND) {
        float cnt = (float)max(g_cnt[g], 1);
        v = pool[g * ND + c] / cnt;
    } else {
        v = rdkit[(size_t)g * RDM + (c - ND)];
    }
    out[idx] = v;
}

// ---------------- final layer: [G,256] @ [256,1] -----------------------------
__global__ void final_dot_kernel(const float* __restrict__ m2,
                                 const float* __restrict__ w3,
                                 const float* __restrict__ b3,
                                 float* __restrict__ out, int G) {
    int warp = (blockIdx.x * blockDim.x + threadIdx.x) >> 5;
    int lane = threadIdx.x & 31;
    if (warp >= G) return;
    int g = warp;
    float s = 0.f;
#pragma unroll
    for (int c = lane; c < H2; c += 32) s += m2[(size_t)g * H2 + c] * w3[c];
#pragma unroll
    for (int off = 16; off > 0; off >>= 1) s += __shfl_xor_sync(0xFFFFFFFFu, s, off);
    if (lane == 0) out[g] = s + b3[0];
}

// ---------------- launch ------------------------------------------------------
extern "C" void kernel_launch(void* const* d_in, const int* in_sizes, int n_in,
                              void* d_out, int out_size) {
    const int* x_feat     = (const int*)d_in[0];
    const int* edge_index = (const int*)d_in[1];
    const int* eaf        = (const int*)d_in[2];
    const int* batch      = (const int*)d_in[3];
    const float* rdkit    = (const float*)d_in[4];
    const float* atom_emb = (const float*)d_in[5];
    const float* bond_emb = (const float*)d_in[6];
    const float* c1w1 = (const float*)d_in[7];
    const float* c1b1 = (const float*)d_in[8];
    const float* c1w2 = (const float*)d_in[9];
    const float* c1b2 = (const float*)d_in[10];
    const float* c2w1 = (const float*)d_in[11];
    const float* c2b1 = (const float*)d_in[12];
    const float* c2w2 = (const float*)d_in[13];
    const float* c2b2 = (const float*)d_in[14];
    const float* mw1 = (const float*)d_in[15];
    const float* mb1 = (const float*)d_in[16];
    const float* mw2 = (const float*)d_in[17];
    const float* mb2 = (const float*)d_in[18];
    const float* mw3 = (const float*)d_in[19];
    const float* mb3 = (const float*)d_in[20];
    float* out = (float*)d_out;

    const int N = in_sizes[0] / 9;
    const int E = in_sizes[1] / 2;
    const int G = in_sizes[4] / RDM;

    float *p_x0, *p_agg, *p_x1, *p_x2, *p_pool, *p_min, *p_m1, *p_m2;
    uint4* p_wp;
    cudaGetSymbolAddress((void**)&p_x0, g_x0);
    cudaGetSymbolAddress((void**)&p_agg, g_agg);
    cudaGetSymbolAddress((void**)&p_x1, g_x1);
    cudaGetSymbolAddress((void**)&p_x2, g_x2);
    cudaGetSymbolAddress((void**)&p_pool, g_pool);
    cudaGetSymbolAddress((void**)&p_min, g_min);
    cudaGetSymbolAddress((void**)&p_m1, g_m1);
    cudaGetSymbolAddress((void**)&p_m2, g_m2);
    cudaGetSymbolAddress((void**)&p_wp, g_wp);

    cudaFuncSetAttribute(gemm_fused_kernel,
                         cudaFuncAttributeMaxDynamicSharedMemorySize, FSM);

    const int agg_blocks = (N + 7) / 8;
    const int ntiles = (N + 127) / 128;
    const int encode_blocks = (N * 32 + 255) / 256;
    const int EB = (E + 255) / 256;

    // kernels 1..3 before the profiled gather (= 4th kernel launch)
    prep_combo_kernel<<<256 + EB + encode_blocks, 256>>>(                     // 1
        x_feat, atom_emb, edge_index, eaf, c1w1, c1w2, c2w1, c2w2, p_x0, N, E, EB);
    scan_single_kernel<<<1, 1024>>>(batch, N, E, G);                          // 2
    scatter_kernel<<<(max(E, N) + 255) / 256, 256>>>(edge_index, E, N);       // 3

    // ---- conv1 ----
    agg_gather_kernel<<<agg_blocks, 256>>>(p_x0, bond_emb, p_agg, N);         // 4 (profiled)
    gemm_fused_kernel<<<GEMM_GRID, 256, FSM>>>(p_agg, p_wp + 0 * 4096, p_wp + 1 * 4096,
                                               c1b1, c1b2, p_x1, N, ntiles);

    // ---- conv2 ----
    agg_gather_kernel<<<agg_blocks, 256>>>(p_x1, bond_emb, p_agg, N);
    gemm_fused_kernel<<<GEMM_GRID, 256, FSM>>>(p_agg, p_wp + 2 * 4096, p_wp + 3 * 4096,
                                               c2b1, c2b2, p_x2, N, ntiles);

    // ---- pool + concat ----
    cudaMemsetAsync(p_pool, 0, (size_t)G * ND * sizeof(float), 0);
    pool_sum_kernel<<<(N * 32 + 255) / 256, 256>>>(p_x2, batch, p_pool, N);
    {
        int total = G * KMLP1;
        concat_kernel<<<(total + 255) / 256, 256>>>(p_pool, rdkit, p_min, G);
    }

    // ---- MLP (fp32 SIMT; small) ----
    gemm_kernel<64, 64, 8, 4, 8, true, 1><<<dim3(G / 64, H1 / 64), 128>>>(
        p_min, mw1, mb1, p_m1, G, KMLP1, H1);
    gemm_kernel<64, 64, 8, 4, 8, true, 1><<<dim3(G / 64, H2 / 64), 128>>>(
        p_m1, mw2, mb2, p_m2, G, H1, H2);
    final_dot_kernel<<<(G * 32 + 255) / 256, 256>>>(p_m2, mw3, mb3, out, G);

    (void)n_in; (void)out_size;
}

// round 14
// speedup vs baseline: 1.1322x; 1.1322x over previous
#include <cuda_runtime.h>
#include <cuda_fp16.h>
#include <cstdint>

// Problem constants (fixed by the dataset)
#define ND 128
#define NMAX 50000
#define EMAX 640000
#define GMAX 1024
#define RDM 200
#define H1 512
#define H2 256
#define KMLP1 (ND + RDM)   // 328

// ---------------- scratch (device globals; no allocation allowed) ----------
__device__ float g_x0[NMAX * ND];
__device__ float g_agg[NMAX * ND];
__device__ float g_x1[NMAX * ND];
__device__ float g_x2[NMAX * ND];
__device__ float g_pool[GMAX * ND];
__device__ int   g_cnt[GMAX];
__device__ float g_min[GMAX * KMLP1];
__device__ float g_m1[GMAX * H1];
__device__ float g_m2[GMAX * H2];
// prepped conv weights: per matrix 64KB = Wt hi (32KB) + Wt lo (32KB), [n][k] fp16
__device__ uint4 g_wp[4][4096];
// CSR sort scratch. g_deg is zero at the START of every execution:
// zero-initialized at module load; re-zeroed by scatter_kernel at the end of
// each run (after the scan has consumed it). Deterministic across replays.
__device__ int g_deg[NMAX];
__device__ int g_off[NMAX + 1];
__device__ int g_pos[NMAX];
__device__ int g_part[64];
__device__ int g_emeta[EMAX];    // packed per-edge meta (src | f0<<16 | f1<<20 | f2<<24)
__device__ int g_smeta[EMAX];    // meta in dst-sorted order

// ---------------- helpers ----------------------------------------------------
__device__ __forceinline__ unsigned long long pack2(float x, float y) {
    unsigned long long r;
    asm("mov.b64 %0, {%1, %2};" : "=l"(r) : "f"(x), "f"(y));
    return r;
}
__device__ __forceinline__ void unpack2(unsigned long long v, float& x, float& y) {
    asm("mov.b64 {%0, %1}, %2;" : "=f"(x), "=f"(y) : "l"(v));
}
__device__ __forceinline__ void ffma2(unsigned long long& d, unsigned long long a,
                                      unsigned long long b) {
    asm("fma.rn.f32x2 %0, %1, %2, %0;" : "+l"(d) : "l"(a), "l"(b));
}
__device__ __forceinline__ void red_add_v4(float* p, float a, float b, float c, float d) {
    asm volatile("red.global.add.v4.f32 [%0], {%1, %2, %3, %4};"
                 :: "l"(p), "f"(a), "f"(b), "f"(c), "f"(d) : "memory");
}
// hi/lo fp16x2 split of two floats (a=elem0/.x, b=elem1/.y)
__device__ __forceinline__ uint32_t hilo16(float a, float b, uint32_t& lopack) {
    __half2 h2 = __floats2half2_rn(a, b);
    float2 f = __half22float2(h2);
    __half2 l2 = __floats2half2_rn(a - f.x, b - f.y);
    lopack = *reinterpret_cast<uint32_t*>(&l2);
    return *reinterpret_cast<uint32_t*>(&h2);
}
// warp-level fp16 tensor-core mma (baseline PTX, works on plain sm_103)
__device__ __forceinline__ void mma16816(float* c, const uint32_t* a, const uint32_t* b) {
    asm volatile(
        "mma.sync.aligned.m16n8k16.row.col.f32.f16.f16.f32 "
        "{%0,%1,%2,%3}, {%4,%5,%6,%7}, {%8,%9}, {%0,%1,%2,%3};"
        : "+f"(c[0]), "+f"(c[1]), "+f"(c[2]), "+f"(c[3])
        : "r"(a[0]), "r"(a[1]), "r"(a[2]), "r"(a[3]), "r"(b[0]), "r"(b[1]));
}

// ---------------- launch 1: combo — wprep | atom encode | edge prep ----------
// blocks [0,256): W prep; [256, 256+EB): edge prep; rest: atom encode.
// g_deg is guaranteed zero at kernel start (see its declaration comment).
__global__ void prep_combo_kernel(const int* __restrict__ xf,
                                  const float* __restrict__ aemb,
                                  const int* __restrict__ ei,
                                  const int* __restrict__ eaf,
                                  const float* __restrict__ w0, const float* __restrict__ w1,
                                  const float* __restrict__ w2, const float* __restrict__ w3,
                                  float* __restrict__ xout, int N, int E, int EB) {
    if (blockIdx.x < 256) {
        int widx = blockIdx.x >> 6;
        int idx = (blockIdx.x & 63) * 256 + threadIdx.x;   // 0..16383
        const float* W = (widx == 0) ? w0 : (widx == 1) ? w1 : (widx == 2) ? w2 : w3;
        int n = idx >> 7, k = idx & 127;
        float w = W[k * 128 + n];
        __half h = __float2half_rn(w);
        __half l = __float2half_rn(w - __half2float(h));
        __half* base = reinterpret_cast<__half*>(&g_wp[widx][0]);
        base[n * 128 + k] = h;
        base[16384 + n * 128 + k] = l;
        return;
    }
    if ((int)blockIdx.x < 256 + EB) {
        int e = (blockIdx.x - 256) * 256 + threadIdx.x;
        if (e >= E) return;
        int src = ei[e];
        int dst = ei[E + e];
        int f0 = eaf[e * 3 + 0], f1 = eaf[e * 3 + 1], f2 = eaf[e * 3 + 2];
        g_emeta[e] = src | (f0 << 16) | (f1 << 20) | (f2 << 24);
        atomicAdd(&g_deg[dst], 1);
        return;
    }
    // atom encoder (no atomics)
    int warp = ((blockIdx.x - 256 - EB) * blockDim.x + threadIdx.x) >> 5;
    int lane = threadIdx.x & 31;
    if (warp >= N) return;
    int n = warp;
    float4 acc = make_float4(0.f, 0.f, 0.f, 0.f);
#pragma unroll
    for (int f = 0; f < 9; f++) {
        int id = xf[n * 9 + f];
        const float4* row = reinterpret_cast<const float4*>(aemb + ((f << 6) + id) * ND);
        float4 v = row[lane];
        acc.x += v.x; acc.y += v.y; acc.z += v.z; acc.w += v.w;
    }
    reinterpret_cast<float4*>(xout + (size_t)n * ND)[lane] = acc;
}

// ---------------- launch 2: per-block exclusive scan --------------------------
__global__ void scan1_kernel(int N) {
    __shared__ int sm[1024];
    int i = blockIdx.x * 1024 + threadIdx.x;
    int v = (i < N) ? g_deg[i] : 0;
    sm[threadIdx.x] = v;
    __syncthreads();
#pragma unroll
    for (int ofs = 1; ofs < 1024; ofs <<= 1) {
        int t = (threadIdx.x >= ofs) ? sm[threadIdx.x - ofs] : 0;
        __syncthreads();
        sm[threadIdx.x] += t;
        __syncthreads();
    }
    if (i < N) g_off[i] = sm[threadIdx.x] - v;   // exclusive (block-local)
    if (threadIdx.x == 1023) g_part[blockIdx.x] = sm[1023];
}

// ---------------- launch 3: apply partials (parallel) + graph counts ---------
__global__ void scan23_kernel(const int* __restrict__ batch, int N, int E, int G, int nb) {
    __shared__ int sp[64];
    const int tid = threadIdx.x;
    if (tid < 64) sp[tid] = (tid < nb) ? g_part[tid] : 0;
    __syncthreads();
#pragma unroll
    for (int ofs = 1; ofs < 64; ofs <<= 1) {
        int t = (tid >= ofs && tid < 64) ? sp[tid - ofs] : 0;
        __syncthreads();
        if (tid < 64) sp[tid] += t;
        __syncthreads();
    }
    int pref = (blockIdx.x == 0) ? 0 : sp[blockIdx.x - 1];
    int i = blockIdx.x * 1024 + tid;
    if (i < N) {
        int v = g_off[i] + pref;
        g_off[i] = v;
        g_pos[i] = v;
    }
    if (i == 0) g_off[N] = E;
    // graph counts via binary search on sorted batch (block 0 only)
    if (blockIdx.x == 0 && tid < G) {
        int g = tid;
        int lo = 0, hi = N;
        while (lo < hi) { int mid = (lo + hi) >> 1; if (batch[mid] < g) lo = mid + 1; else hi = mid; }
        int lo2 = lo, hi2 = N;
        while (lo2 < hi2) { int mid = (lo2 + hi2) >> 1; if (batch[mid] <= g) lo2 = mid + 1; else hi2 = mid; }
        g_cnt[g] = lo2 - lo;
    }
}

// ---------------- launch 4: scatter meta into dst-sorted order ---------------
// Also re-zeros g_deg for the next execution (deg is dead after the scan).
__global__ void scatter_kernel(const int* __restrict__ ei, int E, int N) {
    int e = blockIdx.x * blockDim.x + threadIdx.x;
    if (e < N) g_deg[e] = 0;
    if (e >= E) return;
    int dst = ei[E + e];
    int p = atomicAdd(&g_pos[dst], 1);
    g_smeta[p] = g_emeta[e];
}

// ---------------- launch 5: gather-aggregate (persistent, smem bonds) --------
// out[n] = x[n] + sum relu(x[src]+bond). Bonds staged in smem ONCE per block
// (fp32, 24.6KB x 296 blocks = 7MB total staging); x[src] through L1tex.
#define AGG_GRID 296
__global__ void __launch_bounds__(256)
agg_gather_kernel(const float* __restrict__ xin, const float* __restrict__ bemb,
                  float* __restrict__ out, int N) {
    __shared__ float4 s_bond[48][32];   // 24.6KB fp32 (exact)
    for (int i = threadIdx.x; i < 48 * 32; i += 256) {
        int r = i >> 5, c = i & 31;
        s_bond[r][c] = reinterpret_cast<const float4*>(bemb + r * 128)[c];
    }
    __syncthreads();

    int wid = threadIdx.x >> 5, lane = threadIdx.x & 31;
    for (int n = blockIdx.x * 8 + wid; n < N; n += AGG_GRID * 8) {
        int s = g_off[n], e_end = g_off[n + 1];
        float4 acc = reinterpret_cast<const float4*>(xin + (size_t)n * ND)[lane];
        for (int base = s; base < e_end; base += 32) {
            int cnt = min(32, e_end - base);
            int mb = (lane < cnt) ? g_smeta[base + lane] : 0;
            int i = 0;
#define ACC_EDGE(m, xs)                                                         \
            {                                                                   \
                float4 b0 = s_bond[((m) >> 16) & 15][lane];                     \
                float4 b1 = s_bond[16 + (((m) >> 20) & 15)][lane];              \
                float4 b2 = s_bond[32 + (((m) >> 24) & 15)][lane];              \
                acc.x += fmaxf((xs).x + b0.x + b1.x + b2.x, 0.f);               \
                acc.y += fmaxf((xs).y + b0.y + b1.y + b2.y, 0.f);               \
                acc.z += fmaxf((xs).z + b0.z + b1.z + b2.z, 0.f);               \
                acc.w += fmaxf((xs).w + b0.w + b1.w + b2.w, 0.f);               \
            }
            for (; i + 4 <= cnt; i += 4) {
                int m0 = __shfl_sync(0xFFFFFFFFu, mb, i);
                int m1 = __shfl_sync(0xFFFFFFFFu, mb, i + 1);
                int m2 = __shfl_sync(0xFFFFFFFFu, mb, i + 2);
                int m3 = __shfl_sync(0xFFFFFFFFu, mb, i + 3);
                float4 xs0 = reinterpret_cast<const float4*>(xin + (size_t)(m0 & 0xFFFF) * ND)[lane];
                float4 xs1 = reinterpret_cast<const float4*>(xin + (size_t)(m1 & 0xFFFF) * ND)[lane];
                float4 xs2 = reinterpret_cast<const float4*>(xin + (size_t)(m2 & 0xFFFF) * ND)[lane];
                float4 xs3 = reinterpret_cast<const float4*>(xin + (size_t)(m3 & 0xFFFF) * ND)[lane];
                ACC_EDGE(m0, xs0)
                ACC_EDGE(m1, xs1)
                ACC_EDGE(m2, xs2)
                ACC_EDGE(m3, xs3)
            }
            for (; i < cnt; i++) {
                int m = __shfl_sync(0xFFFFFFFFu, mb, i);
                float4 xs = reinterpret_cast<const float4*>(xin + (size_t)(m & 0xFFFF) * ND)[lane];
                ACC_EDGE(m, xs)
            }
#undef ACC_EDGE
        }
        reinterpret_cast<float4*>(out + (size_t)n * ND)[lane] = acc;
    }
}

// ---------------- persistent fused 2-layer tensor-core conv GEMM -------------
// C = relu(A @ W1 + b1) @ W2 + b2; fp16 3-chain (AhiWhi + AloWhi + AhiWlo).
#define SAK 136   // padded fp16 stride (272B rows)
#define TTILE (128 * SAK * 2)      // 34816 B
#define FSM (6 * TTILE)            // Ahi,Alo,W1hi,W1lo,W2hi,W2lo = 208896 B
#define GEMM_GRID 148

__global__ void __launch_bounds__(256, 1)
gemm_fused_kernel(const float* __restrict__ A,
                  const uint4* __restrict__ Wp1, const uint4* __restrict__ Wp2,
                  const float* __restrict__ b1, const float* __restrict__ b2,
                  float* __restrict__ C, int M, int ntiles) {
    extern __shared__ char dsm[];
    __shared__ float s_b1[128];
    __shared__ float s_b2[128];

    char* pAhi  = dsm;
    char* pAlo  = dsm + 1 * TTILE;
    char* pW1hi = dsm + 2 * TTILE;
    char* pW1lo = dsm + 3 * TTILE;
    char* pW2hi = dsm + 4 * TTILE;
    char* pW2lo = dsm + 5 * TTILE;
    const uint32_t* sAhi = (const uint32_t*)pAhi;
    const uint32_t* sAlo = (const uint32_t*)pAlo;

    const int tid = threadIdx.x, wid = tid >> 5, lane = tid & 31;
    const int g = lane >> 2, q = lane & 3;
    const int wm = wid & 3, wn = wid >> 2;

    if (tid < 128) { s_b1[tid] = b1[tid]; s_b2[tid] = b2[tid]; }

    // ---- stage W1, W2 once (hi + lo, 32KB each part) ----
#pragma unroll
    for (int i = 0; i < 8; i++) {
        int u = tid + i * 256;              // 0..2047
        int n = u >> 4, kc = u & 15;
        *(uint4*)(pW1hi + n * (SAK * 2) + kc * 16) = Wp1[u];
        *(uint4*)(pW1lo + n * (SAK * 2) + kc * 16) = Wp1[u + 2048];
        *(uint4*)(pW2hi + n * (SAK * 2) + kc * 16) = Wp2[u];
        *(uint4*)(pW2lo + n * (SAK * 2) + kc * 16) = Wp2[u + 2048];
    }

    const int ra0 = wm * 32 + g;
    const int nb0 = wn * 64 + g;

    for (int t = blockIdx.x; t < ntiles; t += GEMM_GRID) {
        const int brow = t * 128;
        __syncthreads();   // W ready (1st iter) / prior tile's readers done

        // ---- stage A: fp32 -> hi/lo fp16 ----
        {
            int row = tid >> 1;
            int c0 = (tid & 1) * 64;
            bool valid = (brow + row) < M;
            const float4* a4 = (const float4*)(A + (size_t)(brow + row) * 128 + c0);
            char* dAh = pAhi + row * (SAK * 2) + c0 * 2;
            char* dAl = pAlo + row * (SAK * 2) + c0 * 2;
#pragma unroll
            for (int i = 0; i < 8; i++) {
                float4 v0 = make_float4(0.f, 0.f, 0.f, 0.f), v1 = v0;
                if (valid) { v0 = a4[i * 2]; v1 = a4[i * 2 + 1]; }
                uint4 h, l;
                h.x = hilo16(v0.x, v0.y, l.x);
                h.y = hilo16(v0.z, v0.w, l.y);
                h.z = hilo16(v1.x, v1.y, l.z);
                h.w = hilo16(v1.z, v1.w, l.w);
                *(uint4*)(dAh + i * 16) = h;
                *(uint4*)(dAl + i * 16) = l;
            }
        }
        __syncthreads();

        float acc[2][8][4];

        // ================= layer 1 =================
#pragma unroll
        for (int mt = 0; mt < 2; mt++)
#pragma unroll
            for (int nt = 0; nt < 8; nt++)
#pragma unroll
                for (int j = 0; j < 4; j++) acc[mt][nt][j] = 0.f;

        {
            const uint32_t* sWhi = (const uint32_t*)pW1hi;
            const uint32_t* sWlo = (const uint32_t*)pW1lo;
#pragma unroll
            for (int ks = 0; ks < 8; ks++) {
                const int k0 = ks * 16 + q * 2;
                uint32_t ah[2][4], al[2][4];
#pragma unroll
                for (int mt = 0; mt < 2; mt++) {
                    int r = ra0 + mt * 16;
                    int i00 = (r * SAK + k0) >> 1;
                    int i10 = ((r + 8) * SAK + k0) >> 1;
                    ah[mt][0] = sAhi[i00];     ah[mt][1] = sAhi[i10];
                    ah[mt][2] = sAhi[i00 + 4]; ah[mt][3] = sAhi[i10 + 4];
                    al[mt][0] = sAlo[i00];     al[mt][1] = sAlo[i10];
                    al[mt][2] = sAlo[i00 + 4]; al[mt][3] = sAlo[i10 + 4];
                }
#pragma unroll
                for (int nt = 0; nt < 8; nt++) {
                    int n = nb0 + nt * 8;
                    int ib = (n * SAK + k0) >> 1;
                    uint32_t bh[2], bl[2];
                    bh[0] = sWhi[ib]; bh[1] = sWhi[ib + 4];
                    bl[0] = sWlo[ib]; bl[1] = sWlo[ib + 4];
#pragma unroll
                    for (int mt = 0; mt < 2; mt++) {
                        mma16816(acc[mt][nt], ah[mt], bh);
                        mma16816(acc[mt][nt], al[mt], bh);
                        mma16816(acc[mt][nt], ah[mt], bl);
                    }
                }
            }
        }
        __syncthreads();   // everyone done reading A tiles before overwrite

        // ---- h = relu(acc + b1) -> hi/lo fp16 back into A buffers ----
#pragma unroll
        for (int mt = 0; mt < 2; mt++) {
            int r0 = wm * 32 + mt * 16 + g;
#pragma unroll
            for (int nt = 0; nt < 8; nt++) {
                int col = wn * 64 + nt * 8 + q * 2;
                float bx = s_b1[col], by = s_b1[col + 1];
                float x0 = fmaxf(acc[mt][nt][0] + bx, 0.f);
                float y0 = fmaxf(acc[mt][nt][1] + by, 0.f);
                float x1 = fmaxf(acc[mt][nt][2] + bx, 0.f);
                float y1 = fmaxf(acc[mt][nt][3] + by, 0.f);
                uint32_t l0, l1;
                uint32_t h0 = hilo16(x0, y0, l0);
                uint32_t h1 = hilo16(x1, y1, l1);
                uint32_t o0 = (uint32_t)(r0 * SAK + col) * 2u;
                uint32_t o1 = (uint32_t)((r0 + 8) * SAK + col) * 2u;
                *(uint32_t*)(pAhi + o0) = h0;
                *(uint32_t*)(pAlo + o0) = l0;
                *(uint32_t*)(pAhi + o1) = h1;
                *(uint32_t*)(pAlo + o1) = l1;
            }
        }
        __syncthreads();

        // ================= layer 2 =================
#pragma unroll
        for (int mt = 0; mt < 2; mt++)
#pragma unroll
            for (int nt = 0; nt < 8; nt++)
#pragma unroll
                for (int j = 0; j < 4; j++) acc[mt][nt][j] = 0.f;

        {
            const uint32_t* sWhi = (const uint32_t*)pW2hi;
            const uint32_t* sWlo = (const uint32_t*)pW2lo;
#pragma unroll
            for (int ks = 0; ks < 8; ks++) {
                const int k0 = ks * 16 + q * 2;
                uint32_t ah[2][4], al[2][4];
#pragma unroll
                for (int mt = 0; mt < 2; mt++) {
                    int r = ra0 + mt * 16;
                    int i00 = (r * SAK + k0) >> 1;
                    int i10 = ((r + 8) * SAK + k0) >> 1;
                    ah[mt][0] = sAhi[i00];     ah[mt][1] = sAhi[i10];
                    ah[mt][2] = sAhi[i00 + 4]; ah[mt][3] = sAhi[i10 + 4];
                    al[mt][0] = sAlo[i00];     al[mt][1] = sAlo[i10];
                    al[mt][2] = sAlo[i00 + 4]; al[mt][3] = sAlo[i10 + 4];
                }
#pragma unroll
                for (int nt = 0; nt < 8; nt++) {
                    int n = nb0 + nt * 8;
                    int ib = (n * SAK + k0) >> 1;
                    uint32_t bh[2], bl[2];
                    bh[0] = sWhi[ib]; bh[1] = sWhi[ib + 4];
                    bl[0] = sWlo[ib]; bl[1] = sWlo[ib + 4];
#pragma unroll
                    for (int mt = 0; mt < 2; mt++) {
                        mma16816(acc[mt][nt], ah[mt], bh);
                        mma16816(acc[mt][nt], al[mt], bh);
                        mma16816(acc[mt][nt], ah[mt], bl);
                    }
                }
            }
        }

        // ---- epilogue: C = acc + b2 ----
#pragma unroll
        for (int mt = 0; mt < 2; mt++) {
            int r0 = brow + wm * 32 + mt * 16 + g;
#pragma unroll
            for (int nt = 0; nt < 8; nt++) {
                int col = wn * 64 + nt * 8 + q * 2;
                float bx = s_b2[col], by = s_b2[col + 1];
                if (r0 < M) {
                    float2 o; o.x = acc[mt][nt][0] + bx; o.y = acc[mt][nt][1] + by;
                    *(float2*)(C + (size_t)r0 * 128 + col) = o;
                }
                if (r0 + 8 < M) {
                    float2 o; o.x = acc[mt][nt][2] + bx; o.y = acc[mt][nt][3] + by;
                    *(float2*)(C + (size_t)(r0 + 8) * 128 + col) = o;
                }
            }
        }
    }
}

// ---------------- fp32 GEMM (MLP only) --------------------------------------
template <int BM, int BN, int BK, int TM, int TN, bool RELU, int MINB>
__global__ void __launch_bounds__((BM / TM) * (BN / TN), MINB)
gemm_kernel(const float* __restrict__ A,
            const float* __restrict__ W, const float* __restrict__ bias,
            float* __restrict__ C, int M, int K, int Nc) {
    constexpr int THREADS = (BM / TM) * (BN / TN);
    __shared__ float sA[BK][BM + 4];
    __shared__ float sW[BK][BN];

    const int tid = threadIdx.x;
    const int tn = tid % (BN / TN);
    const int tm = tid / (BN / TN);
    const int row0 = tm * TM;
    const int col0 = tn * TN;
    const int brow = blockIdx.x * BM;
    const int bcol = blockIdx.y * BN;

    unsigned long long acc[TM][TN / 2];
#pragma unroll
    for (int i = 0; i < TM; i++)
#pragma unroll
        for (int j = 0; j < TN / 2; j++) acc[i][j] = 0ull;

    for (int k0 = 0; k0 < K; k0 += BK) {
        constexpr int A_LOADS = (BM * BK / 4) / THREADS;
#pragma unroll
        for (int i = 0; i < A_LOADS; i++) {
            int idx = tid + i * THREADS;
            int m = idx / (BK / 4);
            int kq = idx % (BK / 4);
            int grow = brow + m;
            float4 v = make_float4(0.f, 0.f, 0.f, 0.f);
            if (grow < M)
                v = *reinterpret_cast<const float4*>(A + (size_t)grow * K + k0 + kq * 4);
            sA[kq * 4 + 0][m] = v.x;
            sA[kq * 4 + 1][m] = v.y;
            sA[kq * 4 + 2][m] = v.z;
            sA[kq * 4 + 3][m] = v.w;
        }
        constexpr int W_LOADS = (BK * BN / 4) / THREADS;
#pragma unroll
        for (int i = 0; i < W_LOADS; i++) {
            int idx = tid + i * THREADS;
            int kk = idx / (BN / 4);
            int cq = idx % (BN / 4);
            *reinterpret_cast<float4*>(&sW[kk][cq * 4]) =
                *reinterpret_cast<const float4*>(W + (size_t)(k0 + kk) * Nc + bcol + cq * 4);
        }
        __syncthreads();

#pragma unroll
        for (int kk = 0; kk < BK; kk++) {
            float a[TM];
#pragma unroll
            for (int i = 0; i < TM; i += 4) {
                float4 t = *reinterpret_cast<const float4*>(&sA[kk][row0 + i]);
                a[i] = t.x; a[i + 1] = t.y; a[i + 2] = t.z; a[i + 3] = t.w;
            }
            unsigned long long wv[TN / 2];
#pragma unroll
            for (int j = 0; j < TN; j += 4) {
                float4 t = *reinterpret_cast<const float4*>(&sW[kk][col0 + j]);
                wv[j / 2] = pack2(t.x, t.y);
                wv[j / 2 + 1] = pack2(t.z, t.w);
            }
#pragma unroll
            for (int i = 0; i < TM; i++) {
                unsigned long long ad = pack2(a[i], a[i]);
#pragma unroll
                for (int j = 0; j < TN / 2; j++) ffma2(acc[i][j], ad, wv[j]);
            }
        }
        __syncthreads();
    }

    float2 bv[TN / 2];
#pragma unroll
    for (int j = 0; j < TN / 2; j++)
        bv[j] = *reinterpret_cast<const float2*>(bias + bcol + col0 + 2 * j);
#pragma unroll
    for (int i = 0; i < TM; i++) {
        int grow = brow + row0 + i;
        if (grow >= M) continue;
#pragma unroll
        for (int j = 0; j < TN / 2; j++) {
            float x, y;
            unpack2(acc[i][j], x, y);
            x += bv[j].x; y += bv[j].y;
            if (RELU) { x = fmaxf(x, 0.f); y = fmaxf(y, 0.f); }
            float2 o; o.x = x; o.y = y;
            *reinterpret_cast<float2*>(C + (size_t)grow * Nc + bcol + col0 + 2 * j) = o;
        }
    }
}

// ---------------- pooling: sum per graph -------------------------------------
__global__ void pool_sum_kernel(const float* __restrict__ x,
                                const int* __restrict__ batch,
                                float* __restrict__ pool, int N) {
    int warp = (blockIdx.x * blockDim.x + threadIdx.x) >> 5;
    int lane = threadIdx.x & 31;
    if (warp >= N) return;
    int n = warp;
    int g = batch[n];
    float4 v = reinterpret_cast<const float4*>(x + (size_t)n * ND)[lane];
    float* p = pool + (size_t)g * ND + lane * 4;
    red_add_v4(p, v.x, v.y, v.z, v.w);
}

// ---------------- concat: pooled mean + rdkit --------------------------------
__global__ void concat_kernel(const float* __restrict__ pool,
                              const float* __restrict__ rdkit,
                              float* __restrict__ out, int G) {
    int idx = blockIdx.x * blockDim.x + threadIdx.x;
    int total = G * KMLP1;
    if (idx >= total) return;
    int g = idx / KMLP1;
    int c = idx - g * KMLP1;
    float v;
    if (c < ND) {
        float cnt = (float)max(g_cnt[g], 1);
        v = pool[g * ND + c] / cnt;
    } else {
        v = rdkit[(size_t)g * RDM + (c - ND)];
    }
    out[idx] = v;
}

// ---------------- final layer: [G,256] @ [256,1] -----------------------------
__global__ void final_dot_kernel(const float* __restrict__ m2,
                                 const float* __restrict__ w3,
                                 const float* __restrict__ b3,
                                 float* __restrict__ out, int G) {
    int warp = (blockIdx.x * blockDim.x + threadIdx.x) >> 5;
    int lane = threadIdx.x & 31;
    if (warp >= G) return;
    int g = warp;
    float s = 0.f;
#pragma unroll
    for (int c = lane; c < H2; c += 32) s += m2[(size_t)g * H2 + c] * w3[c];
#pragma unroll
    for (int off = 16; off > 0; off >>= 1) s += __shfl_xor_sync(0xFFFFFFFFu, s, off);
    if (lane == 0) out[g] = s + b3[0];
}

// ---------------- launch ------------------------------------------------------
extern "C" void kernel_launch(void* const* d_in, const int* in_sizes, int n_in,
                              void* d_out, int out_size) {
    const int* x_feat     = (const int*)d_in[0];
    const int* edge_index = (const int*)d_in[1];
    const int* eaf        = (const int*)d_in[2];
    const int* batch      = (const int*)d_in[3];
    const float* rdkit    = (const float*)d_in[4];
    const float* atom_emb = (const float*)d_in[5];
    const float* bond_emb = (const float*)d_in[6];
    const float* c1w1 = (const float*)d_in[7];
    const float* c1b1 = (const float*)d_in[8];
    const float* c1w2 = (const float*)d_in[9];
    const float* c1b2 = (const float*)d_in[10];
    const float* c2w1 = (const float*)d_in[11];
    const float* c2b1 = (const float*)d_in[12];
    const float* c2w2 = (const float*)d_in[13];
    const float* c2b2 = (const float*)d_in[14];
    const float* mw1 = (const float*)d_in[15];
    const float* mb1 = (const float*)d_in[16];
    const float* mw2 = (const float*)d_in[17];
    const float* mb2 = (const float*)d_in[18];
    const float* mw3 = (const float*)d_in[19];
    const float* mb3 = (const float*)d_in[20];
    float* out = (float*)d_out;

    const int N = in_sizes[0] / 9;
    const int E = in_sizes[1] / 2;
    const int G = in_sizes[4] / RDM;

    float *p_x0, *p_agg, *p_x1, *p_x2, *p_pool, *p_min, *p_m1, *p_m2;
    uint4* p_wp;
    cudaGetSymbolAddress((void**)&p_x0, g_x0);
    cudaGetSymbolAddress((void**)&p_agg, g_agg);
    cudaGetSymbolAddress((void**)&p_x1, g_x1);
    cudaGetSymbolAddress((void**)&p_x2, g_x2);
    cudaGetSymbolAddress((void**)&p_pool, g_pool);
    cudaGetSymbolAddress((void**)&p_min, g_min);
    cudaGetSymbolAddress((void**)&p_m1, g_m1);
    cudaGetSymbolAddress((void**)&p_m2, g_m2);
    cudaGetSymbolAddress((void**)&p_wp, g_wp);

    cudaFuncSetAttribute(gemm_fused_kernel,
                         cudaFuncAttributeMaxDynamicSharedMemorySize, FSM);

    const int ntiles = (N + 127) / 128;
    const int encode_blocks = (N * 32 + 255) / 256;
    const int EB = (E + 255) / 256;
    const int scan_blocks = (N + 1023) / 1024;

    prep_combo_kernel<<<256 + EB + encode_blocks, 256>>>(                     // 1
        x_feat, atom_emb, edge_index, eaf, c1w1, c1w2, c2w1, c2w2, p_x0, N, E, EB);
    scan1_kernel<<<scan_blocks, 1024>>>(N);                                   // 2
    scan23_kernel<<<scan_blocks, 1024>>>(batch, N, E, G, scan_blocks);        // 3
    scatter_kernel<<<(max(E, N) + 255) / 256, 256>>>(edge_index, E, N);       // 4

    // ---- conv1 ----
    agg_gather_kernel<<<AGG_GRID, 256>>>(p_x0, bond_emb, p_agg, N);           // 5
    gemm_fused_kernel<<<GEMM_GRID, 256, FSM>>>(p_agg, p_wp + 0 * 4096, p_wp + 1 * 4096,
                                               c1b1, c1b2, p_x1, N, ntiles);

    // ---- conv2 ----
    agg_gather_kernel<<<AGG_GRID, 256>>>(p_x1, bond_emb, p_agg, N);
    gemm_fused_kernel<<<GEMM_GRID, 256, FSM>>>(p_agg, p_wp + 2 * 4096, p_wp + 3 * 4096,
                                               c2b1, c2b2, p_x2, N, ntiles);

    // ---- pool + concat ----
    cudaMemsetAsync(p_pool, 0, (size_t)G * ND * sizeof(float), 0);
    pool_sum_kernel<<<(N * 32 + 255) / 256, 256>>>(p_x2, batch, p_pool, N);
    {
        int total = G * KMLP1;
        concat_kernel<<<(total + 255) / 256, 256>>>(p_pool, rdkit, p_min, G);
    }

    // ---- MLP (fp32 SIMT; small) ----
    gemm_kernel<64, 64, 8, 4, 8, true, 1><<<dim3(G / 64, H1 / 64), 128>>>(
        p_min, mw1, mb1, p_m1, G, KMLP1, H1);
    gemm_kernel<64, 64, 8, 4, 8, true, 1><<<dim3(G / 64, H2 / 64), 128>>>(
        p_m1, mw2, mb2, p_m2, G, H1, H2);
    final_dot_kernel<<<(G * 32 + 255) / 256, 256>>>(p_m2, mw3, mb3, out, G);

    (void)n_in; (void)out_size;
}

// round 15
// speedup vs baseline: 1.2513x; 1.1052x over previous
#include <cuda_runtime.h>
#include <cuda_fp16.h>
#include <cstdint>

// Problem constants (fixed by the dataset)
#define ND 128
#define NMAX 50000
#define EMAX 640000
#define GMAX 1024
#define RDM 200
#define H1 512
#define H2 256
#define KMLP1 (ND + RDM)   // 328

// ---------------- scratch (device globals; no allocation allowed) ----------
__device__ float g_x0[NMAX * ND];
__device__ float g_agg[NMAX * ND];
__device__ float g_x1[NMAX * ND];
__device__ float g_x2[NMAX * ND];
__device__ float g_pool[GMAX * ND];
__device__ int   g_cnt[GMAX];
__device__ float g_min[GMAX * KMLP1];
__device__ float g_m1[GMAX * H1];
__device__ float g_m2[GMAX * H2];
// prepped conv weights: per matrix 64KB = Wt hi (32KB) + Wt lo (32KB), [n][k] fp16
__device__ uint4 g_wp[4][4096];
// combined bond table: bsum[f0|f1<<4|f2<<8][c] = b0[f0][c]+b1[f1][c]+b2[f2][c]
__device__ float g_bsum[4096 * 128];   // 2MB, L2-resident
// CSR sort scratch
__device__ int g_deg[NMAX];
__device__ int g_off[NMAX + 1];
__device__ int g_pos[NMAX];
__device__ int g_part[64];
__device__ int g_emeta[EMAX];    // packed per-edge meta (src | f0<<16 | f1<<20 | f2<<24)
__device__ int g_smeta[EMAX];    // meta in dst-sorted order

// ---------------- helpers ----------------------------------------------------
__device__ __forceinline__ unsigned long long pack2(float x, float y) {
    unsigned long long r;
    asm("mov.b64 %0, {%1, %2};" : "=l"(r) : "f"(x), "f"(y));
    return r;
}
__device__ __forceinline__ void unpack2(unsigned long long v, float& x, float& y) {
    asm("mov.b64 {%0, %1}, %2;" : "=f"(x), "=f"(y) : "l"(v));
}
__device__ __forceinline__ void ffma2(unsigned long long& d, unsigned long long a,
                                      unsigned long long b) {
    asm("fma.rn.f32x2 %0, %1, %2, %0;" : "+l"(d) : "l"(a), "l"(b));
}
__device__ __forceinline__ void red_add_v4(float* p, float a, float b, float c, float d) {
    asm volatile("red.global.add.v4.f32 [%0], {%1, %2, %3, %4};"
                 :: "l"(p), "f"(a), "f"(b), "f"(c), "f"(d) : "memory");
}
// hi/lo fp16x2 split of two floats (a=elem0/.x, b=elem1/.y)
__device__ __forceinline__ uint32_t hilo16(float a, float b, uint32_t& lopack) {
    __half2 h2 = __floats2half2_rn(a, b);
    float2 f = __half22float2(h2);
    __half2 l2 = __floats2half2_rn(a - f.x, b - f.y);
    lopack = *reinterpret_cast<uint32_t*>(&l2);
    return *reinterpret_cast<uint32_t*>(&h2);
}
// warp-level fp16 tensor-core mma (baseline PTX, works on plain sm_103)
__device__ __forceinline__ void mma16816(float* c, const uint32_t* a, const uint32_t* b) {
    asm volatile(
        "mma.sync.aligned.m16n8k16.row.col.f32.f16.f16.f32 "
        "{%0,%1,%2,%3}, {%4,%5,%6,%7}, {%8,%9}, {%0,%1,%2,%3};"
        : "+f"(c[0]), "+f"(c[1]), "+f"(c[2]), "+f"(c[3])
        : "r"(a[0]), "r"(a[1]), "r"(a[2]), "r"(a[3]), "r"(b[0]), "r"(b[1]));
}

// ---------------- launch 1: combo — wprep | bsum | deg-zero | atom encode ----
// blocks [0,256): W prep; [256,2304): bsum build; [2304,2304+ZB): zero deg; rest: encode.
#define ZB ((NMAX + 255) / 256)
__global__ void prep_combo_kernel(const int* __restrict__ xf,
                                  const float* __restrict__ aemb,
                                  const float* __restrict__ bemb,
                                  const float* __restrict__ w0, const float* __restrict__ w1,
                                  const float* __restrict__ w2, const float* __restrict__ w3,
                                  float* __restrict__ xout, int N) {
    if (blockIdx.x < 256) {
        int widx = blockIdx.x >> 6;
        int idx = (blockIdx.x & 63) * 256 + threadIdx.x;   // 0..16383
        const float* W = (widx == 0) ? w0 : (widx == 1) ? w1 : (widx == 2) ? w2 : w3;
        int n = idx >> 7, k = idx & 127;
        float w = W[k * 128 + n];
        __half h = __float2half_rn(w);
        __half l = __float2half_rn(w - __half2float(h));
        __half* base = reinterpret_cast<__half*>(&g_wp[widx][0]);
        base[n * 128 + k] = h;
        base[16384 + n * 128 + k] = l;
        return;
    }
    if (blockIdx.x < 2304) {
        // combined bond table: code = f0 | f1<<4 | f2<<8
        int idx = (blockIdx.x - 256) * 256 + threadIdx.x;   // 0..524287
        int code = idx >> 7, c = idx & 127;
        int f0 = code & 15, f1 = (code >> 4) & 15, f2 = (code >> 8) & 15;
        g_bsum[idx] = bemb[f0 * 128 + c] + bemb[(16 + f1) * 128 + c]
                    + bemb[(32 + f2) * 128 + c];
        return;
    }
    if (blockIdx.x < 2304 + ZB) {
        int i = (blockIdx.x - 2304) * 256 + threadIdx.x;
        if (i < N) g_deg[i] = 0;
        return;
    }
    // atom encoder (no atomics)
    int warp = ((blockIdx.x - 2304 - ZB) * blockDim.x + threadIdx.x) >> 5;
    int lane = threadIdx.x & 31;
    if (warp >= N) return;
    int n = warp;
    float4 acc = make_float4(0.f, 0.f, 0.f, 0.f);
#pragma unroll
    for (int f = 0; f < 9; f++) {
        int id = xf[n * 9 + f];
        const float4* row = reinterpret_cast<const float4*>(aemb + ((f << 6) + id) * ND);
        float4 v = row[lane];
        acc.x += v.x; acc.y += v.y; acc.z += v.z; acc.w += v.w;
    }
    reinterpret_cast<float4*>(xout + (size_t)n * ND)[lane] = acc;
}

// ---------------- launch 2: pack meta + dst-degree histogram -----------------
__global__ void edge_prep_kernel(const int* __restrict__ ei,
                                 const int* __restrict__ eaf, int E) {
    int e = blockIdx.x * blockDim.x + threadIdx.x;
    if (e >= E) return;
    int src = ei[e];
    int dst = ei[E + e];
    int f0 = eaf[e * 3 + 0], f1 = eaf[e * 3 + 1], f2 = eaf[e * 3 + 2];
    g_emeta[e] = src | (f0 << 16) | (f1 << 20) | (f2 << 24);
    atomicAdd(&g_deg[dst], 1);
}
// ---------------- launch 3: per-block exclusive scan -------------------------
__global__ void scan1_kernel(int N) {
    __shared__ int sm[1024];
    int i = blockIdx.x * 1024 + threadIdx.x;
    int v = (i < N) ? g_deg[i] : 0;
    sm[threadIdx.x] = v;
    __syncthreads();
#pragma unroll
    for (int ofs = 1; ofs < 1024; ofs <<= 1) {
        int t = (threadIdx.x >= ofs) ? sm[threadIdx.x - ofs] : 0;
        __syncthreads();
        sm[threadIdx.x] += t;
        __syncthreads();
    }
    if (i < N) g_off[i] = sm[threadIdx.x] - v;   // exclusive (block-local)
    if (threadIdx.x == 1023) g_part[blockIdx.x] = sm[1023];
}
// ---------------- launch 4: apply partials (parallel) + graph counts ---------
__global__ void scan23_kernel(const int* __restrict__ batch, int N, int E, int G, int nb) {
    __shared__ int sp[64];
    const int tid = threadIdx.x;
    if (tid < 64) sp[tid] = (tid < nb) ? g_part[tid] : 0;
    __syncthreads();
#pragma unroll
    for (int ofs = 1; ofs < 64; ofs <<= 1) {
        int t = (tid >= ofs && tid < 64) ? sp[tid - ofs] : 0;
        __syncthreads();
        if (tid < 64) sp[tid] += t;
        __syncthreads();
    }
    int pref = (blockIdx.x == 0) ? 0 : sp[blockIdx.x - 1];
    int i = blockIdx.x * 1024 + tid;
    if (i < N) {
        int v = g_off[i] + pref;
        g_off[i] = v;
        g_pos[i] = v;
    }
    if (i == 0) g_off[N] = E;
    if (blockIdx.x == 0 && tid < G) {
        int g = tid;
        int lo = 0, hi = N;
        while (lo < hi) { int mid = (lo + hi) >> 1; if (batch[mid] < g) lo = mid + 1; else hi = mid; }
        int lo2 = lo, hi2 = N;
        while (lo2 < hi2) { int mid = (lo2 + hi2) >> 1; if (batch[mid] <= g) lo2 = mid + 1; else hi2 = mid; }
        g_cnt[g] = lo2 - lo;
    }
}
// ---------------- launch 5: scatter meta into dst-sorted order ---------------
__global__ void scatter_kernel(const int* __restrict__ ei, int E) {
    int e = blockIdx.x * blockDim.x + threadIdx.x;
    if (e >= E) return;
    int dst = ei[E + e];
    int p = atomicAdd(&g_pos[dst], 1);
    g_smeta[p] = g_emeta[e];
}

// ---------------- launch 6: gather-aggregate ---------------------------------
// out[n] = x[n] + sum relu(x[src] + bsum[code]); 1 bond row per edge (2MB L2 table).
__global__ void __launch_bounds__(256)
agg_gather_kernel(const float* __restrict__ xin, float* __restrict__ out, int N) {
    int wid = threadIdx.x >> 5, lane = threadIdx.x & 31;
    int n = blockIdx.x * 8 + wid;
    if (n >= N) return;
    int s = g_off[n], e_end = g_off[n + 1];
    float4 acc = reinterpret_cast<const float4*>(xin + (size_t)n * ND)[lane];
    for (int base = s; base < e_end; base += 32) {
        int cnt = min(32, e_end - base);
        int mb = (lane < cnt) ? g_smeta[base + lane] : 0;
        int i = 0;
#define ACC_EDGE(m, xs)                                                                    \
        {                                                                                  \
            float4 bs = __ldg(reinterpret_cast<const float4*>(                             \
                g_bsum + (size_t)(((m) >> 16) & 0xFFF) * ND) + lane);                      \
            acc.x += fmaxf((xs).x + bs.x, 0.f);                                            \
            acc.y += fmaxf((xs).y + bs.y, 0.f);                                            \
            acc.z += fmaxf((xs).z + bs.z, 0.f);                                            \
            acc.w += fmaxf((xs).w + bs.w, 0.f);                                            \
        }
        for (; i + 4 <= cnt; i += 4) {
            int m0 = __shfl_sync(0xFFFFFFFFu, mb, i);
            int m1 = __shfl_sync(0xFFFFFFFFu, mb, i + 1);
            int m2 = __shfl_sync(0xFFFFFFFFu, mb, i + 2);
            int m3 = __shfl_sync(0xFFFFFFFFu, mb, i + 3);
            float4 xs0 = reinterpret_cast<const float4*>(xin + (size_t)(m0 & 0xFFFF) * ND)[lane];
            float4 xs1 = reinterpret_cast<const float4*>(xin + (size_t)(m1 & 0xFFFF) * ND)[lane];
            float4 xs2 = reinterpret_cast<const float4*>(xin + (size_t)(m2 & 0xFFFF) * ND)[lane];
            float4 xs3 = reinterpret_cast<const float4*>(xin + (size_t)(m3 & 0xFFFF) * ND)[lane];
            ACC_EDGE(m0, xs0)
            ACC_EDGE(m1, xs1)
            ACC_EDGE(m2, xs2)
            ACC_EDGE(m3, xs3)
        }
        for (; i < cnt; i++) {
            int m = __shfl_sync(0xFFFFFFFFu, mb, i);
            float4 xs = reinterpret_cast<const float4*>(xin + (size_t)(m & 0xFFFF) * ND)[lane];
            ACC_EDGE(m, xs)
        }
#undef ACC_EDGE
    }
    reinterpret_cast<float4*>(out + (size_t)n * ND)[lane] = acc;
}

// ---------------- persistent fused 2-layer tensor-core conv GEMM -------------
// C = relu(A @ W1 + b1) @ W2 + b2; fp16 3-chain (AhiWhi + AloWhi + AhiWlo).
#define SAK 136   // padded fp16 stride (272B rows)
#define TTILE (128 * SAK * 2)      // 34816 B
#define FSM (6 * TTILE)            // Ahi,Alo,W1hi,W1lo,W2hi,W2lo = 208896 B
#define GEMM_GRID 148

__global__ void __launch_bounds__(256, 1)
gemm_fused_kernel(const float* __restrict__ A,
                  const uint4* __restrict__ Wp1, const uint4* __restrict__ Wp2,
                  const float* __restrict__ b1, const float* __restrict__ b2,
                  float* __restrict__ C, int M, int ntiles) {
    extern __shared__ char dsm[];
    __shared__ float s_b1[128];
    __shared__ float s_b2[128];

    char* pAhi  = dsm;
    char* pAlo  = dsm + 1 * TTILE;
    char* pW1hi = dsm + 2 * TTILE;
    char* pW1lo = dsm + 3 * TTILE;
    char* pW2hi = dsm + 4 * TTILE;
    char* pW2lo = dsm + 5 * TTILE;
    const uint32_t* sAhi = (const uint32_t*)pAhi;
    const uint32_t* sAlo = (const uint32_t*)pAlo;

    const int tid = threadIdx.x, wid = tid >> 5, lane = tid & 31;
    const int g = lane >> 2, q = lane & 3;
    const int wm = wid & 3, wn = wid >> 2;

    if (tid < 128) { s_b1[tid] = b1[tid]; s_b2[tid] = b2[tid]; }

    // ---- stage W1, W2 once (hi + lo, 32KB each part) ----
#pragma unroll
    for (int i = 0; i < 8; i++) {
        int u = tid + i * 256;              // 0..2047
        int n = u >> 4, kc = u & 15;
        *(uint4*)(pW1hi + n * (SAK * 2) + kc * 16) = Wp1[u];
        *(uint4*)(pW1lo + n * (SAK * 2) + kc * 16) = Wp1[u + 2048];
        *(uint4*)(pW2hi + n * (SAK * 2) + kc * 16) = Wp2[u];
        *(uint4*)(pW2lo + n * (SAK * 2) + kc * 16) = Wp2[u + 2048];
    }

    const int ra0 = wm * 32 + g;
    const int nb0 = wn * 64 + g;

    for (int t = blockIdx.x; t < ntiles; t += GEMM_GRID) {
        const int brow = t * 128;
        __syncthreads();   // W ready (1st iter) / prior tile's readers done

        // ---- stage A: fp32 -> hi/lo fp16 ----
        {
            int row = tid >> 1;
            int c0 = (tid & 1) * 64;
            bool valid = (brow + row) < M;
            const float4* a4 = (const float4*)(A + (size_t)(brow + row) * 128 + c0);
            char* dAh = pAhi + row * (SAK * 2) + c0 * 2;
            char* dAl = pAlo + row * (SAK * 2) + c0 * 2;
#pragma unroll
            for (int i = 0; i < 8; i++) {
                float4 v0 = make_float4(0.f, 0.f, 0.f, 0.f), v1 = v0;
                if (valid) { v0 = a4[i * 2]; v1 = a4[i * 2 + 1]; }
                uint4 h, l;
                h.x = hilo16(v0.x, v0.y, l.x);
                h.y = hilo16(v0.z, v0.w, l.y);
                h.z = hilo16(v1.x, v1.y, l.z);
                h.w = hilo16(v1.z, v1.w, l.w);
                *(uint4*)(dAh + i * 16) = h;
                *(uint4*)(dAl + i * 16) = l;
            }
        }
        __syncthreads();

        float acc[2][8][4];

        // ================= layer 1 =================
#pragma unroll
        for (int mt = 0; mt < 2; mt++)
#pragma unroll
            for (int nt = 0; nt < 8; nt++)
#pragma unroll
                for (int j = 0; j < 4; j++) acc[mt][nt][j] = 0.f;

        {
            const uint32_t* sWhi = (const uint32_t*)pW1hi;
            const uint32_t* sWlo = (const uint32_t*)pW1lo;
#pragma unroll
            for (int ks = 0; ks < 8; ks++) {
                const int k0 = ks * 16 + q * 2;
                uint32_t ah[2][4], al[2][4];
#pragma unroll
                for (int mt = 0; mt < 2; mt++) {
                    int r = ra0 + mt * 16;
                    int i00 = (r * SAK + k0) >> 1;
                    int i10 = ((r + 8) * SAK + k0) >> 1;
                    ah[mt][0] = sAhi[i00];     ah[mt][1] = sAhi[i10];
                    ah[mt][2] = sAhi[i00 + 4]; ah[mt][3] = sAhi[i10 + 4];
                    al[mt][0] = sAlo[i00];     al[mt][1] = sAlo[i10];
                    al[mt][2] = sAlo[i00 + 4]; al[mt][3] = sAlo[i10 + 4];
                }
#pragma unroll
                for (int nt = 0; nt < 8; nt++) {
                    int n = nb0 + nt * 8;
                    int ib = (n * SAK + k0) >> 1;
                    uint32_t bh[2], bl[2];
                    bh[0] = sWhi[ib]; bh[1] = sWhi[ib + 4];
                    bl[0] = sWlo[ib]; bl[1] = sWlo[ib + 4];
#pragma unroll
                    for (int mt = 0; mt < 2; mt++) {
                        mma16816(acc[mt][nt], ah[mt], bh);
                        mma16816(acc[mt][nt], al[mt], bh);
                        mma16816(acc[mt][nt], ah[mt], bl);
                    }
                }
            }
        }
        __syncthreads();   // everyone done reading A tiles before overwrite

        // ---- h = relu(acc + b1) -> hi/lo fp16 back into A buffers ----
#pragma unroll
        for (int mt = 0; mt < 2; mt++) {
            int r0 = wm * 32 + mt * 16 + g;
#pragma unroll
            for (int nt = 0; nt < 8; nt++) {
                int col = wn * 64 + nt * 8 + q * 2;
                float bx = s_b1[col], by = s_b1[col + 1];
                float x0 = fmaxf(acc[mt][nt][0] + bx, 0.f);
                float y0 = fmaxf(acc[mt][nt][1] + by, 0.f);
                float x1 = fmaxf(acc[mt][nt][2] + bx, 0.f);
                float y1 = fmaxf(acc[mt][nt][3] + by, 0.f);
                uint32_t l0, l1;
                uint32_t h0 = hilo16(x0, y0, l0);
                uint32_t h1 = hilo16(x1, y1, l1);
                uint32_t o0 = (uint32_t)(r0 * SAK + col) * 2u;
                uint32_t o1 = (uint32_t)((r0 + 8) * SAK + col) * 2u;
                *(uint32_t*)(pAhi + o0) = h0;
                *(uint32_t*)(pAlo + o0) = l0;
                *(uint32_t*)(pAhi + o1) = h1;
                *(uint32_t*)(pAlo + o1) = l1;
            }
        }
        __syncthreads();

        // ================= layer 2 =================
#pragma unroll
        for (int mt = 0; mt < 2; mt++)
#pragma unroll
            for (int nt = 0; nt < 8; nt++)
#pragma unroll
                for (int j = 0; j < 4; j++) acc[mt][nt][j] = 0.f;

        {
            const uint32_t* sWhi = (const uint32_t*)pW2hi;
            const uint32_t* sWlo = (const uint32_t*)pW2lo;
#pragma unroll
            for (int ks = 0; ks < 8; ks++) {
                const int k0 = ks * 16 + q * 2;
                uint32_t ah[2][4], al[2][4];
#pragma unroll
                for (int mt = 0; mt < 2; mt++) {
                    int r = ra0 + mt * 16;
                    int i00 = (r * SAK + k0) >> 1;
                    int i10 = ((r + 8) * SAK + k0) >> 1;
                    ah[mt][0] = sAhi[i00];     ah[mt][1] = sAhi[i10];
                    ah[mt][2] = sAhi[i00 + 4]; ah[mt][3] = sAhi[i10 + 4];
                    al[mt][0] = sAlo[i00];     al[mt][1] = sAlo[i10];
                    al[mt][2] = sAlo[i00 + 4]; al[mt][3] = sAlo[i10 + 4];
                }
#pragma unroll
                for (int nt = 0; nt < 8; nt++) {
                    int n = nb0 + nt * 8;
                    int ib = (n * SAK + k0) >> 1;
                    uint32_t bh[2], bl[2];
                    bh[0] = sWhi[ib]; bh[1] = sWhi[ib + 4];
                    bl[0] = sWlo[ib]; bl[1] = sWlo[ib + 4];
#pragma unroll
                    for (int mt = 0; mt < 2; mt++) {
                        mma16816(acc[mt][nt], ah[mt], bh);
                        mma16816(acc[mt][nt], al[mt], bh);
                        mma16816(acc[mt][nt], ah[mt], bl);
                    }
                }
            }
        }

        // ---- epilogue: C = acc + b2 ----
#pragma unroll
        for (int mt = 0; mt < 2; mt++) {
            int r0 = brow + wm * 32 + mt * 16 + g;
#pragma unroll
            for (int nt = 0; nt < 8; nt++) {
                int col = wn * 64 + nt * 8 + q * 2;
                float bx = s_b2[col], by = s_b2[col + 1];
                if (r0 < M) {
                    float2 o; o.x = acc[mt][nt][0] + bx; o.y = acc[mt][nt][1] + by;
                    *(float2*)(C + (size_t)r0 * 128 + col) = o;
                }
                if (r0 + 8 < M) {
                    float2 o; o.x = acc[mt][nt][2] + bx; o.y = acc[mt][nt][3] + by;
                    *(float2*)(C + (size_t)(r0 + 8) * 128 + col) = o;
                }
            }
        }
    }
}

// ---------------- fp32 GEMM (MLP only) --------------------------------------
template <int BM, int BN, int BK, int TM, int TN, bool RELU, int MINB>
__global__ void __launch_bounds__((BM / TM) * (BN / TN), MINB)
gemm_kernel(const float* __restrict__ A,
            const float* __restrict__ W, const float* __restrict__ bias,
            float* __restrict__ C, int M, int K, int Nc) {
    constexpr int THREADS = (BM / TM) * (BN / TN);
    __shared__ float sA[BK][BM + 4];
    __shared__ float sW[BK][BN];

    const int tid = threadIdx.x;
    const int tn = tid % (BN / TN);
    const int tm = tid / (BN / TN);
    const int row0 = tm * TM;
    const int col0 = tn * TN;
    const int brow = blockIdx.x * BM;
    const int bcol = blockIdx.y * BN;

    unsigned long long acc[TM][TN / 2];
#pragma unroll
    for (int i = 0; i < TM; i++)
#pragma unroll
        for (int j = 0; j < TN / 2; j++) acc[i][j] = 0ull;

    for (int k0 = 0; k0 < K; k0 += BK) {
        constexpr int A_LOADS = (BM * BK / 4) / THREADS;
#pragma unroll
        for (int i = 0; i < A_LOADS; i++) {
            int idx = tid + i * THREADS;
            int m = idx / (BK / 4);
            int kq = idx % (BK / 4);
            int grow = brow + m;
            float4 v = make_float4(0.f, 0.f, 0.f, 0.f);
            if (grow < M)
                v = *reinterpret_cast<const float4*>(A + (size_t)grow * K + k0 + kq * 4);
            sA[kq * 4 + 0][m] = v.x;
            sA[kq * 4 + 1][m] = v.y;
            sA[kq * 4 + 2][m] = v.z;
            sA[kq * 4 + 3][m] = v.w;
        }
        constexpr int W_LOADS = (BK * BN / 4) / THREADS;
#pragma unroll
        for (int i = 0; i < W_LOADS; i++) {
            int idx = tid + i * THREADS;
            int kk = idx / (BN / 4);
            int cq = idx % (BN / 4);
            *reinterpret_cast<float4*>(&sW[kk][cq * 4]) =
                *reinterpret_cast<const float4*>(W + (size_t)(k0 + kk) * Nc + bcol + cq * 4);
        }
        __syncthreads();

#pragma unroll
        for (int kk = 0; kk < BK; kk++) {
            float a[TM];
#pragma unroll
            for (int i = 0; i < TM; i += 4) {
                float4 t = *reinterpret_cast<const float4*>(&sA[kk][row0 + i]);
                a[i] = t.x; a[i + 1] = t.y; a[i + 2] = t.z; a[i + 3] = t.w;
            }
            unsigned long long wv[TN / 2];
#pragma unroll
            for (int j = 0; j < TN; j += 4) {
                float4 t = *reinterpret_cast<const float4*>(&sW[kk][col0 + j]);
                wv[j / 2] = pack2(t.x, t.y);
                wv[j / 2 + 1] = pack2(t.z, t.w);
            }
#pragma unroll
            for (int i = 0; i < TM; i++) {
                unsigned long long ad = pack2(a[i], a[i]);
#pragma unroll
                for (int j = 0; j < TN / 2; j++) ffma2(acc[i][j], ad, wv[j]);
            }
        }
        __syncthreads();
    }

    float2 bv[TN / 2];
#pragma unroll
    for (int j = 0; j < TN / 2; j++)
        bv[j] = *reinterpret_cast<const float2*>(bias + bcol + col0 + 2 * j);
#pragma unroll
    for (int i = 0; i < TM; i++) {
        int grow = brow + row0 + i;
        if (grow >= M) continue;
#pragma unroll
        for (int j = 0; j < TN / 2; j++) {
            float x, y;
            unpack2(acc[i][j], x, y);
            x += bv[j].x; y += bv[j].y;
            if (RELU) { x = fmaxf(x, 0.f); y = fmaxf(y, 0.f); }
            float2 o; o.x = x; o.y = y;
            *reinterpret_cast<float2*>(C + (size_t)grow * Nc + bcol + col0 + 2 * j) = o;
        }
    }
}

// ---------------- pooling: sum per graph -------------------------------------
__global__ void pool_sum_kernel(const float* __restrict__ x,
                                const int* __restrict__ batch,
                                float* __restrict__ pool, int N) {
    int warp = (blockIdx.x * blockDim.x + threadIdx.x) >> 5;
    int lane = threadIdx.x & 31;
    if (warp >= N) return;
    int n = warp;
    int g = batch[n];
    float4 v = reinterpret_cast<const float4*>(x + (size_t)n * ND)[lane];
    float* p = pool + (size_t)g * ND + lane * 4;
    red_add_v4(p, v.x, v.y, v.z, v.w);
}

// ---------------- concat: pooled mean + rdkit --------------------------------
__global__ void concat_kernel(const float* __restrict__ pool,
                              const float* __restrict__ rdkit,
                              float* __restrict__ out, int G) {
    int idx = blockIdx.x * blockDim.x + threadIdx.x;
    int total = G * KMLP1;
    if (idx >= total) return;
    int g = idx / KMLP1;
    int c = idx - g * KMLP1;
    float v;
    if (c < ND) {
        float cnt = (float)max(g_cnt[g], 1);
        v = pool[g * ND + c] / cnt;
    } else {
        v = rdkit[(size_t)g * RDM + (c - ND)];
    }
    out[idx] = v;
}

// ---------------- final layer: [G,256] @ [256,1] -----------------------------
__global__ void final_dot_kernel(const float* __restrict__ m2,
                                 const float* __restrict__ w3,
                                 const float* __restrict__ b3,
                                 float* __restrict__ out, int G) {
    int warp = (blockIdx.x * blockDim.x + threadIdx.x) >> 5;
    int lane = threadIdx.x & 31;
    if (warp >= G) return;
    int g = warp;
    float s = 0.f;
#pragma unroll
    for (int c = lane; c < H2; c += 32) s += m2[(size_t)g * H2 + c] * w3[c];
#pragma unroll
    for (int off = 16; off > 0; off >>= 1) s += __shfl_xor_sync(0xFFFFFFFFu, s, off);
    if (lane == 0) out[g] = s + b3[0];
}

// ---------------- launch ------------------------------------------------------
extern "C" void kernel_launch(void* const* d_in, const int* in_sizes, int n_in,
                              void* d_out, int out_size) {
    const int* x_feat     = (const int*)d_in[0];
    const int* edge_index = (const int*)d_in[1];
    const int* eaf        = (const int*)d_in[2];
    const int* batch      = (const int*)d_in[3];
    const float* rdkit    = (const float*)d_in[4];
    const float* atom_emb = (const float*)d_in[5];
    const float* bond_emb = (const float*)d_in[6];
    const float* c1w1 = (const float*)d_in[7];
    const float* c1b1 = (const float*)d_in[8];
    const float* c1w2 = (const float*)d_in[9];
    const float* c1b2 = (const float*)d_in[10];
    const float* c2w1 = (const float*)d_in[11];
    const float* c2b1 = (const float*)d_in[12];
    const float* c2w2 = (const float*)d_in[13];
    const float* c2b2 = (const float*)d_in[14];
    const float* mw1 = (const float*)d_in[15];
    const float* mb1 = (const float*)d_in[16];
    const float* mw2 = (const float*)d_in[17];
    const float* mb2 = (const float*)d_in[18];
    const float* mw3 = (const float*)d_in[19];
    const float* mb3 = (const float*)d_in[20];
    float* out = (float*)d_out;

    const int N = in_sizes[0] / 9;
    const int E = in_sizes[1] / 2;
    const int G = in_sizes[4] / RDM;

    float *p_x0, *p_agg, *p_x1, *p_x2, *p_pool, *p_min, *p_m1, *p_m2;
    uint4* p_wp;
    cudaGetSymbolAddress((void**)&p_x0, g_x0);
    cudaGetSymbolAddress((void**)&p_agg, g_agg);
    cudaGetSymbolAddress((void**)&p_x1, g_x1);
    cudaGetSymbolAddress((void**)&p_x2, g_x2);
    cudaGetSymbolAddress((void**)&p_pool, g_pool);
    cudaGetSymbolAddress((void**)&p_min, g_min);
    cudaGetSymbolAddress((void**)&p_m1, g_m1);
    cudaGetSymbolAddress((void**)&p_m2, g_m2);
    cudaGetSymbolAddress((void**)&p_wp, g_wp);

    cudaFuncSetAttribute(gemm_fused_kernel,
                         cudaFuncAttributeMaxDynamicSharedMemorySize, FSM);

    const int agg_blocks = (N + 7) / 8;
    const int ntiles = (N + 127) / 128;
    const int encode_blocks = (N * 32 + 255) / 256;
    const int scan_blocks = (N + 1023) / 1024;

    prep_combo_kernel<<<2304 + ZB + encode_blocks, 256>>>(                    // 1
        x_feat, atom_emb, bond_emb, c1w1, c1w2, c2w1, c2w2, p_x0, N);
    edge_prep_kernel<<<(E + 255) / 256, 256>>>(edge_index, eaf, E);           // 2
    scan1_kernel<<<scan_blocks, 1024>>>(N);                                   // 3
    scan23_kernel<<<scan_blocks, 1024>>>(batch, N, E, G, scan_blocks);        // 4
    scatter_kernel<<<(E + 255) / 256, 256>>>(edge_index, E);                  // 5

    // ---- conv1 ----
    agg_gather_kernel<<<agg_blocks, 256>>>(p_x0, p_agg, N);                   // 6
    gemm_fused_kernel<<<GEMM_GRID, 256, FSM>>>(p_agg, p_wp + 0 * 4096, p_wp + 1 * 4096,
                                               c1b1, c1b2, p_x1, N, ntiles);

    // ---- conv2 ----
    agg_gather_kernel<<<agg_blocks, 256>>>(p_x1, p_agg, N);
    gemm_fused_kernel<<<GEMM_GRID, 256, FSM>>>(p_agg, p_wp + 2 * 4096, p_wp + 3 * 4096,
                                               c2b1, c2b2, p_x2, N, ntiles);

    // ---- pool + concat ----
    cudaMemsetAsync(p_pool, 0, (size_t)G * ND * sizeof(float), 0);
    pool_sum_kernel<<<(N * 32 + 255) / 256, 256>>>(p_x2, batch, p_pool, N);
    {
        int total = G * KMLP1;
        concat_kernel<<<(total + 255) / 256, 256>>>(p_pool, rdkit, p_min, G);
    }

    // ---- MLP (fp32 SIMT; small) ----
    gemm_kernel<64, 64, 8, 4, 8, true, 1><<<dim3(G / 64, H1 / 64), 128>>>(
        p_min, mw1, mb1, p_m1, G, KMLP1, H1);
    gemm_kernel<64, 64, 8, 4, 8, true, 1><<<dim3(G / 64, H2 / 64), 128>>>(
        p_m1, mw2, mb2, p_m2, G, H1, H2);
    final_dot_kernel<<<(G * 32 + 255) / 256, 256>>>(p_m2, mw3, mb3, out, G);

    (void)n_in; (void)out_size;
}

// round 16
// speedup vs baseline: 1.2843x; 1.0264x over previous
#include <cuda_runtime.h>
#include <cuda_fp16.h>
#include <cstdint>

// Problem constants (fixed by the dataset)
#define ND 128
#define NMAX 50000
#define EMAX 640000
#define GMAX 1024
#define RDM 200
#define H1 512
#define H2 256
#define KMLP1 (ND + RDM)   // 328

// ---------------- scratch (device globals; no allocation allowed) ----------
__device__ float g_x0[NMAX * ND];
__device__ float g_agg[NMAX * ND];
__device__ float g_x1[NMAX * ND];
__device__ float g_x2[NMAX * ND];
__device__ float g_min[GMAX * KMLP1];
__device__ float g_m1[GMAX * H1];
__device__ float g_m2[GMAX * H2];
// prepped conv weights: per matrix 64KB = Wt hi (32KB) + Wt lo (32KB), [n][k] fp16
__device__ uint4 g_wp[4][4096];
// combined bond table: bsum[f0|f1<<4|f2<<8][c] = b0[f0][c]+b1[f1][c]+b2[f2][c]
__device__ float g_bsum[4096 * 128];   // 2MB, L2-resident
// CSR sort scratch
__device__ int g_deg[NMAX];
__device__ int g_off[NMAX + 1];
__device__ int g_pos[NMAX];
__device__ int g_part[64];
__device__ int g_emeta[EMAX];    // packed per-edge meta (src | f0<<16 | f1<<20 | f2<<24)
__device__ int g_smeta[EMAX];    // meta in dst-sorted order

// ---------------- helpers ----------------------------------------------------
__device__ __forceinline__ unsigned long long pack2(float x, float y) {
    unsigned long long r;
    asm("mov.b64 %0, {%1, %2};" : "=l"(r) : "f"(x), "f"(y));
    return r;
}
__device__ __forceinline__ void unpack2(unsigned long long v, float& x, float& y) {
    asm("mov.b64 {%0, %1}, %2;" : "=f"(x), "=f"(y) : "l"(v));
}
__device__ __forceinline__ void ffma2(unsigned long long& d, unsigned long long a,
                                      unsigned long long b) {
    asm("fma.rn.f32x2 %0, %1, %2, %0;" : "+l"(d) : "l"(a), "l"(b));
}
// hi/lo fp16x2 split of two floats (a=elem0/.x, b=elem1/.y)
__device__ __forceinline__ uint32_t hilo16(float a, float b, uint32_t& lopack) {
    __half2 h2 = __floats2half2_rn(a, b);
    float2 f = __half22float2(h2);
    __half2 l2 = __floats2half2_rn(a - f.x, b - f.y);
    lopack = *reinterpret_cast<uint32_t*>(&l2);
    return *reinterpret_cast<uint32_t*>(&h2);
}
// warp-level fp16 tensor-core mma (baseline PTX, works on plain sm_103)
__device__ __forceinline__ void mma16816(float* c, const uint32_t* a, const uint32_t* b) {
    asm volatile(
        "mma.sync.aligned.m16n8k16.row.col.f32.f16.f16.f32 "
        "{%0,%1,%2,%3}, {%4,%5,%6,%7}, {%8,%9}, {%0,%1,%2,%3};"
        : "+f"(c[0]), "+f"(c[1]), "+f"(c[2]), "+f"(c[3])
        : "r"(a[0]), "r"(a[1]), "r"(a[2]), "r"(a[3]), "r"(b[0]), "r"(b[1]));
}

// ---------------- launch 1: combo — wprep | bsum | deg-zero | atom encode ----
#define ZB ((NMAX + 255) / 256)
__global__ void prep_combo_kernel(const int* __restrict__ xf,
                                  const float* __restrict__ aemb,
                                  const float* __restrict__ bemb,
                                  const float* __restrict__ w0, const float* __restrict__ w1,
                                  const float* __restrict__ w2, const float* __restrict__ w3,
                                  float* __restrict__ xout, int N) {
    if (blockIdx.x < 256) {
        int widx = blockIdx.x >> 6;
        int idx = (blockIdx.x & 63) * 256 + threadIdx.x;   // 0..16383
        const float* W = (widx == 0) ? w0 : (widx == 1) ? w1 : (widx == 2) ? w2 : w3;
        int n = idx >> 7, k = idx & 127;
        float w = W[k * 128 + n];
        __half h = __float2half_rn(w);
        __half l = __float2half_rn(w - __half2float(h));
        __half* base = reinterpret_cast<__half*>(&g_wp[widx][0]);
        base[n * 128 + k] = h;
        base[16384 + n * 128 + k] = l;
        return;
    }
    if (blockIdx.x < 2304) {
        int idx = (blockIdx.x - 256) * 256 + threadIdx.x;   // 0..524287
        int code = idx >> 7, c = idx & 127;
        int f0 = code & 15, f1 = (code >> 4) & 15, f2 = (code >> 8) & 15;
        g_bsum[idx] = bemb[f0 * 128 + c] + bemb[(16 + f1) * 128 + c]
                    + bemb[(32 + f2) * 128 + c];
        return;
    }
    if (blockIdx.x < 2304 + ZB) {
        int i = (blockIdx.x - 2304) * 256 + threadIdx.x;
        if (i < N) g_deg[i] = 0;
        return;
    }
    // atom encoder (no atomics)
    int warp = ((blockIdx.x - 2304 - ZB) * blockDim.x + threadIdx.x) >> 5;
    int lane = threadIdx.x & 31;
    if (warp >= N) return;
    int n = warp;
    float4 acc = make_float4(0.f, 0.f, 0.f, 0.f);
#pragma unroll
    for (int f = 0; f < 9; f++) {
        int id = xf[n * 9 + f];
        const float4* row = reinterpret_cast<const float4*>(aemb + ((f << 6) + id) * ND);
        float4 v = row[lane];
        acc.x += v.x; acc.y += v.y; acc.z += v.z; acc.w += v.w;
    }
    reinterpret_cast<float4*>(xout + (size_t)n * ND)[lane] = acc;
}

// ---------------- launch 2: pack meta + dst-degree histogram -----------------
__global__ void edge_prep_kernel(const int* __restrict__ ei,
                                 const int* __restrict__ eaf, int E) {
    int e = blockIdx.x * blockDim.x + threadIdx.x;
    if (e >= E) return;
    int src = ei[e];
    int dst = ei[E + e];
    int f0 = eaf[e * 3 + 0], f1 = eaf[e * 3 + 1], f2 = eaf[e * 3 + 2];
    g_emeta[e] = src | (f0 << 16) | (f1 << 20) | (f2 << 24);
    atomicAdd(&g_deg[dst], 1);
}
// ---------------- launch 3: per-block exclusive scan -------------------------
__global__ void scan1_kernel(int N) {
    __shared__ int sm[1024];
    int i = blockIdx.x * 1024 + threadIdx.x;
    int v = (i < N) ? g_deg[i] : 0;
    sm[threadIdx.x] = v;
    __syncthreads();
#pragma unroll
    for (int ofs = 1; ofs < 1024; ofs <<= 1) {
        int t = (threadIdx.x >= ofs) ? sm[threadIdx.x - ofs] : 0;
        __syncthreads();
        sm[threadIdx.x] += t;
        __syncthreads();
    }
    if (i < N) g_off[i] = sm[threadIdx.x] - v;   // exclusive (block-local)
    if (threadIdx.x == 1023) g_part[blockIdx.x] = sm[1023];
}
// ---------------- launch 4: apply partials (parallel scan of partials) -------
__global__ void scan23_kernel(int N, int E, int nb) {
    __shared__ int sp[64];
    const int tid = threadIdx.x;
    if (tid < 64) sp[tid] = (tid < nb) ? g_part[tid] : 0;
    __syncthreads();
#pragma unroll
    for (int ofs = 1; ofs < 64; ofs <<= 1) {
        int t = (tid >= ofs && tid < 64) ? sp[tid - ofs] : 0;
        __syncthreads();
        if (tid < 64) sp[tid] += t;
        __syncthreads();
    }
    int pref = (blockIdx.x == 0) ? 0 : sp[blockIdx.x - 1];
    int i = blockIdx.x * 1024 + tid;
    if (i < N) {
        int v = g_off[i] + pref;
        g_off[i] = v;
        g_pos[i] = v;
    }
    if (i == 0) g_off[N] = E;
}
// ---------------- launch 5: scatter meta into dst-sorted order ---------------
__global__ void scatter_kernel(const int* __restrict__ ei, int E) {
    int e = blockIdx.x * blockDim.x + threadIdx.x;
    if (e >= E) return;
    int dst = ei[E + e];
    int p = atomicAdd(&g_pos[dst], 1);
    g_smeta[p] = g_emeta[e];
}

// ---------------- launch 6: gather-aggregate ---------------------------------
// out[n] = x[n] + sum relu(x[src] + bsum[code]); 1 bond row per edge (2MB L2 table).
__global__ void __launch_bounds__(256)
agg_gather_kernel(const float* __restrict__ xin, float* __restrict__ out, int N) {
    int wid = threadIdx.x >> 5, lane = threadIdx.x & 31;
    int n = blockIdx.x * 8 + wid;
    if (n >= N) return;
    int s = g_off[n], e_end = g_off[n + 1];
    float4 acc = reinterpret_cast<const float4*>(xin + (size_t)n * ND)[lane];
    for (int base = s; base < e_end; base += 32) {
        int cnt = min(32, e_end - base);
        int mb = (lane < cnt) ? g_smeta[base + lane] : 0;
        int i = 0;
#define ACC_EDGE(m, xs)                                                                    \
        {                                                                                  \
            float4 bs = __ldg(reinterpret_cast<const float4*>(                             \
                g_bsum + (size_t)(((m) >> 16) & 0xFFF) * ND) + lane);                      \
            acc.x += fmaxf((xs).x + bs.x, 0.f);                                            \
            acc.y += fmaxf((xs).y + bs.y, 0.f);                                            \
            acc.z += fmaxf((xs).z + bs.z, 0.f);                                            \
            acc.w += fmaxf((xs).w + bs.w, 0.f);                                            \
        }
        for (; i + 4 <= cnt; i += 4) {
            int m0 = __shfl_sync(0xFFFFFFFFu, mb, i);
            int m1 = __shfl_sync(0xFFFFFFFFu, mb, i + 1);
            int m2 = __shfl_sync(0xFFFFFFFFu, mb, i + 2);
            int m3 = __shfl_sync(0xFFFFFFFFu, mb, i + 3);
            float4 xs0 = reinterpret_cast<const float4*>(xin + (size_t)(m0 & 0xFFFF) * ND)[lane];
            float4 xs1 = reinterpret_cast<const float4*>(xin + (size_t)(m1 & 0xFFFF) * ND)[lane];
            float4 xs2 = reinterpret_cast<const float4*>(xin + (size_t)(m2 & 0xFFFF) * ND)[lane];
            float4 xs3 = reinterpret_cast<const float4*>(xin + (size_t)(m3 & 0xFFFF) * ND)[lane];
            ACC_EDGE(m0, xs0)
            ACC_EDGE(m1, xs1)
            ACC_EDGE(m2, xs2)
            ACC_EDGE(m3, xs3)
        }
        for (; i < cnt; i++) {
            int m = __shfl_sync(0xFFFFFFFFu, mb, i);
            float4 xs = reinterpret_cast<const float4*>(xin + (size_t)(m & 0xFFFF) * ND)[lane];
            ACC_EDGE(m, xs)
        }
#undef ACC_EDGE
    }
    reinterpret_cast<float4*>(out + (size_t)n * ND)[lane] = acc;
}

// ---------------- persistent fused 2-layer tensor-core conv GEMM -------------
// C = relu(A @ W1 + b1) @ W2 + b2; fp16 3-chain (AhiWhi + AloWhi + AhiWlo).
#define SAK 136   // padded fp16 stride (272B rows)
#define TTILE (128 * SAK * 2)      // 34816 B
#define FSM (6 * TTILE)            // Ahi,Alo,W1hi,W1lo,W2hi,W2lo = 208896 B
#define GEMM_GRID 148

__global__ void __launch_bounds__(256, 1)
gemm_fused_kernel(const float* __restrict__ A,
                  const uint4* __restrict__ Wp1, const uint4* __restrict__ Wp2,
                  const float* __restrict__ b1, const float* __restrict__ b2,
                  float* __restrict__ C, int M, int ntiles) {
    extern __shared__ char dsm[];
    __shared__ float s_b1[128];
    __shared__ float s_b2[128];

    char* pAhi  = dsm;
    char* pAlo  = dsm + 1 * TTILE;
    char* pW1hi = dsm + 2 * TTILE;
    char* pW1lo = dsm + 3 * TTILE;
    char* pW2hi = dsm + 4 * TTILE;
    char* pW2lo = dsm + 5 * TTILE;
    const uint32_t* sAhi = (const uint32_t*)pAhi;
    const uint32_t* sAlo = (const uint32_t*)pAlo;

    const int tid = threadIdx.x, wid = tid >> 5, lane = tid & 31;
    const int g = lane >> 2, q = lane & 3;
    const int wm = wid & 3, wn = wid >> 2;

    if (tid < 128) { s_b1[tid] = b1[tid]; s_b2[tid] = b2[tid]; }

    // ---- stage W1, W2 once (hi + lo, 32KB each part) ----
#pragma unroll
    for (int i = 0; i < 8; i++) {
        int u = tid + i * 256;              // 0..2047
        int n = u >> 4, kc = u & 15;
        *(uint4*)(pW1hi + n * (SAK * 2) + kc * 16) = Wp1[u];
        *(uint4*)(pW1lo + n * (SAK * 2) + kc * 16) = Wp1[u + 2048];
        *(uint4*)(pW2hi + n * (SAK * 2) + kc * 16) = Wp2[u];
        *(uint4*)(pW2lo + n * (SAK * 2) + kc * 16) = Wp2[u + 2048];
    }

    const int ra0 = wm * 32 + g;
    const int nb0 = wn * 64 + g;

    for (int t = blockIdx.x; t < ntiles; t += GEMM_GRID) {
        const int brow = t * 128;
        __syncthreads();   // W ready (1st iter) / prior tile's readers done

        // ---- stage A: fp32 -> hi/lo fp16 ----
        {
            int row = tid >> 1;
            int c0 = (tid & 1) * 64;
            bool valid = (brow + row) < M;
            const float4* a4 = (const float4*)(A + (size_t)(brow + row) * 128 + c0);
            char* dAh = pAhi + row * (SAK * 2) + c0 * 2;
            char* dAl = pAlo + row * (SAK * 2) + c0 * 2;
#pragma unroll
            for (int i = 0; i < 8; i++) {
                float4 v0 = make_float4(0.f, 0.f, 0.f, 0.f), v1 = v0;
                if (valid) { v0 = a4[i * 2]; v1 = a4[i * 2 + 1]; }
                uint4 h, l;
                h.x = hilo16(v0.x, v0.y, l.x);
                h.y = hilo16(v0.z, v0.w, l.y);
                h.z = hilo16(v1.x, v1.y, l.z);
                h.w = hilo16(v1.z, v1.w, l.w);
                *(uint4*)(dAh + i * 16) = h;
                *(uint4*)(dAl + i * 16) = l;
            }
        }
        __syncthreads();

        float acc[2][8][4];

        // ================= layer 1 =================
#pragma unroll
        for (int mt = 0; mt < 2; mt++)
#pragma unroll
            for (int nt = 0; nt < 8; nt++)
#pragma unroll
                for (int j = 0; j < 4; j++) acc[mt][nt][j] = 0.f;

        {
            const uint32_t* sWhi = (const uint32_t*)pW1hi;
            const uint32_t* sWlo = (const uint32_t*)pW1lo;
#pragma unroll
            for (int ks = 0; ks < 8; ks++) {
                const int k0 = ks * 16 + q * 2;
                uint32_t ah[2][4], al[2][4];
#pragma unroll
                for (int mt = 0; mt < 2; mt++) {
                    int r = ra0 + mt * 16;
                    int i00 = (r * SAK + k0) >> 1;
                    int i10 = ((r + 8) * SAK + k0) >> 1;
                    ah[mt][0] = sAhi[i00];     ah[mt][1] = sAhi[i10];
                    ah[mt][2] = sAhi[i00 + 4]; ah[mt][3] = sAhi[i10 + 4];
                    al[mt][0] = sAlo[i00];     al[mt][1] = sAlo[i10];
                    al[mt][2] = sAlo[i00 + 4]; al[mt][3] = sAlo[i10 + 4];
                }
#pragma unroll
                for (int nt = 0; nt < 8; nt++) {
                    int n = nb0 + nt * 8;
                    int ib = (n * SAK + k0) >> 1;
                    uint32_t bh[2], bl[2];
                    bh[0] = sWhi[ib]; bh[1] = sWhi[ib + 4];
                    bl[0] = sWlo[ib]; bl[1] = sWlo[ib + 4];
#pragma unroll
                    for (int mt = 0; mt < 2; mt++) {
                        mma16816(acc[mt][nt], ah[mt], bh);
                        mma16816(acc[mt][nt], al[mt], bh);
                        mma16816(acc[mt][nt], ah[mt], bl);
                    }
                }
            }
        }
        __syncthreads();   // everyone done reading A tiles before overwrite

        // ---- h = relu(acc + b1) -> hi/lo fp16 back into A buffers ----
#pragma unroll
        for (int mt = 0; mt < 2; mt++) {
            int r0 = wm * 32 + mt * 16 + g;
#pragma unroll
            for (int nt = 0; nt < 8; nt++) {
                int col = wn * 64 + nt * 8 + q * 2;
                float bx = s_b1[col], by = s_b1[col + 1];
                float x0 = fmaxf(acc[mt][nt][0] + bx, 0.f);
                float y0 = fmaxf(acc[mt][nt][1] + by, 0.f);
                float x1 = fmaxf(acc[mt][nt][2] + bx, 0.f);
                float y1 = fmaxf(acc[mt][nt][3] + by, 0.f);
                uint32_t l0, l1;
                uint32_t h0 = hilo16(x0, y0, l0);
                uint32_t h1 = hilo16(x1, y1, l1);
                uint32_t o0 = (uint32_t)(r0 * SAK + col) * 2u;
                uint32_t o1 = (uint32_t)((r0 + 8) * SAK + col) * 2u;
                *(uint32_t*)(pAhi + o0) = h0;
                *(uint32_t*)(pAlo + o0) = l0;
                *(uint32_t*)(pAhi + o1) = h1;
                *(uint32_t*)(pAlo + o1) = l1;
            }
        }
        __syncthreads();

        // ================= layer 2 =================
#pragma unroll
        for (int mt = 0; mt < 2; mt++)
#pragma unroll
            for (int nt = 0; nt < 8; nt++)
#pragma unroll
                for (int j = 0; j < 4; j++) acc[mt][nt][j] = 0.f;

        {
            const uint32_t* sWhi = (const uint32_t*)pW2hi;
            const uint32_t* sWlo = (const uint32_t*)pW2lo;
#pragma unroll
            for (int ks = 0; ks < 8; ks++) {
                const int k0 = ks * 16 + q * 2;
                uint32_t ah[2][4], al[2][4];
#pragma unroll
                for (int mt = 0; mt < 2; mt++) {
                    int r = ra0 + mt * 16;
                    int i00 = (r * SAK + k0) >> 1;
                    int i10 = ((r + 8) * SAK + k0) >> 1;
                    ah[mt][0] = sAhi[i00];     ah[mt][1] = sAhi[i10];
                    ah[mt][2] = sAhi[i00 + 4]; ah[mt][3] = sAhi[i10 + 4];
                    al[mt][0] = sAlo[i00];     al[mt][1] = sAlo[i10];
                    al[mt][2] = sAlo[i00 + 4]; al[mt][3] = sAlo[i10 + 4];
                }
#pragma unroll
                for (int nt = 0; nt < 8; nt++) {
                    int n = nb0 + nt * 8;
                    int ib = (n * SAK + k0) >> 1;
                    uint32_t bh[2], bl[2];
                    bh[0] = sWhi[ib]; bh[1] = sWhi[ib + 4];
                    bl[0] = sWlo[ib]; bl[1] = sWlo[ib + 4];
#pragma unroll
                    for (int mt = 0; mt < 2; mt++) {
                        mma16816(acc[mt][nt], ah[mt], bh);
                        mma16816(acc[mt][nt], al[mt], bh);
                        mma16816(acc[mt][nt], ah[mt], bl);
                    }
                }
            }
        }

        // ---- epilogue: C = acc + b2 ----
#pragma unroll
        for (int mt = 0; mt < 2; mt++) {
            int r0 = brow + wm * 32 + mt * 16 + g;
#pragma unroll
            for (int nt = 0; nt < 8; nt++) {
                int col = wn * 64 + nt * 8 + q * 2;
                float bx = s_b2[col], by = s_b2[col + 1];
                if (r0 < M) {
                    float2 o; o.x = acc[mt][nt][0] + bx; o.y = acc[mt][nt][1] + by;
                    *(float2*)(C + (size_t)r0 * 128 + col) = o;
                }
                if (r0 + 8 < M) {
                    float2 o; o.x = acc[mt][nt][2] + bx; o.y = acc[mt][nt][3] + by;
                    *(float2*)(C + (size_t)(r0 + 8) * 128 + col) = o;
                }
            }
        }
    }
}

// ---------------- fused pool + concat: one block per graph -------------------
// batch sorted => nodes of graph g are contiguous [lo, hi). No atomics.
__global__ void __launch_bounds__(128)
pool_concat_kernel(const float* __restrict__ x, const int* __restrict__ batch,
                   const float* __restrict__ rdkit, float* __restrict__ out, int N) {
    const int gidx = blockIdx.x;
    const int c = threadIdx.x;
    // binary search (all threads redundantly; no sync needed)
    int lo = 0, hi = N;
    while (lo < hi) { int mid = (lo + hi) >> 1; if (batch[mid] < gidx) lo = mid + 1; else hi = mid; }
    int lo2 = lo, hi2 = N;
    while (lo2 < hi2) { int mid = (lo2 + hi2) >> 1; if (batch[mid] <= gidx) lo2 = mid + 1; else hi2 = mid; }
    float s = 0.f;
    for (int r = lo; r < lo2; r++) s += x[(size_t)r * ND + c];
    float cnt = (float)max(lo2 - lo, 1);
    out[(size_t)gidx * KMLP1 + c] = s / cnt;
    for (int j = c; j < RDM; j += 128)
        out[(size_t)gidx * KMLP1 + ND + j] = rdkit[(size_t)gidx * RDM + j];
}

// ---------------- fp32 GEMM (MLP only) --------------------------------------
template <int BM, int BN, int BK, int TM, int TN, bool RELU, int MINB>
__global__ void __launch_bounds__((BM / TM) * (BN / TN), MINB)
gemm_kernel(const float* __restrict__ A,
            const float* __restrict__ W, const float* __restrict__ bias,
            float* __restrict__ C, int M, int K, int Nc) {
    constexpr int THREADS = (BM / TM) * (BN / TN);
    __shared__ float sA[BK][BM + 4];
    __shared__ float sW[BK][BN];

    const int tid = threadIdx.x;
    const int tn = tid % (BN / TN);
    const int tm = tid / (BN / TN);
    const int row0 = tm * TM;
    const int col0 = tn * TN;
    const int brow = blockIdx.x * BM;
    const int bcol = blockIdx.y * BN;

    unsigned long long acc[TM][TN / 2];
#pragma unroll
    for (int i = 0; i < TM; i++)
#pragma unroll
        for (int j = 0; j < TN / 2; j++) acc[i][j] = 0ull;

    for (int k0 = 0; k0 < K; k0 += BK) {
        constexpr int A_LOADS = (BM * BK / 4) / THREADS;
#pragma unroll
        for (int i = 0; i < A_LOADS; i++) {
            int idx = tid + i * THREADS;
            int m = idx / (BK / 4);
            int kq = idx % (BK / 4);
            int grow = brow + m;
            float4 v = make_float4(0.f, 0.f, 0.f, 0.f);
            if (grow < M)
                v = *reinterpret_cast<const float4*>(A + (size_t)grow * K + k0 + kq * 4);
            sA[kq * 4 + 0][m] = v.x;
            sA[kq * 4 + 1][m] = v.y;
            sA[kq * 4 + 2][m] = v.z;
            sA[kq * 4 + 3][m] = v.w;
        }
        constexpr int W_LOADS = (BK * BN / 4) / THREADS;
#pragma unroll
        for (int i = 0; i < W_LOADS; i++) {
            int idx = tid + i * THREADS;
            int kk = idx / (BN / 4);
            int cq = idx % (BN / 4);
            *reinterpret_cast<float4*>(&sW[kk][cq * 4]) =
                *reinterpret_cast<const float4*>(W + (size_t)(k0 + kk) * Nc + bcol + cq * 4);
        }
        __syncthreads();

#pragma unroll
        for (int kk = 0; kk < BK; kk++) {
            float a[TM];
#pragma unroll
            for (int i = 0; i < TM; i += 4) {
                float4 t = *reinterpret_cast<const float4*>(&sA[kk][row0 + i]);
                a[i] = t.x; a[i + 1] = t.y; a[i + 2] = t.z; a[i + 3] = t.w;
            }
            unsigned long long wv[TN / 2];
#pragma unroll
            for (int j = 0; j < TN; j += 4) {
                float4 t = *reinterpret_cast<const float4*>(&sW[kk][col0 + j]);
                wv[j / 2] = pack2(t.x, t.y);
                wv[j / 2 + 1] = pack2(t.z, t.w);
            }
#pragma unroll
            for (int i = 0; i < TM; i++) {
                unsigned long long ad = pack2(a[i], a[i]);
#pragma unroll
                for (int j = 0; j < TN / 2; j++) ffma2(acc[i][j], ad, wv[j]);
            }
        }
        __syncthreads();
    }

    float2 bv[TN / 2];
#pragma unroll
    for (int j = 0; j < TN / 2; j++)
        bv[j] = *reinterpret_cast<const float2*>(bias + bcol + col0 + 2 * j);
#pragma unroll
    for (int i = 0; i < TM; i++) {
        int grow = brow + row0 + i;
        if (grow >= M) continue;
#pragma unroll
        for (int j = 0; j < TN / 2; j++) {
            float x, y;
            unpack2(acc[i][j], x, y);
            x += bv[j].x; y += bv[j].y;
            if (RELU) { x = fmaxf(x, 0.f); y = fmaxf(y, 0.f); }
            float2 o; o.x = x; o.y = y;
            *reinterpret_cast<float2*>(C + (size_t)grow * Nc + bcol + col0 + 2 * j) = o;
        }
    }
}

// ---------------- final layer: [G,256] @ [256,1] -----------------------------
__global__ void final_dot_kernel(const float* __restrict__ m2,
                                 const float* __restrict__ w3,
                                 const float* __restrict__ b3,
                                 float* __restrict__ out, int G) {
    int warp = (blockIdx.x * blockDim.x + threadIdx.x) >> 5;
    int lane = threadIdx.x & 31;
    if (warp >= G) return;
    int g = warp;
    float s = 0.f;
#pragma unroll
    for (int c = lane; c < H2; c += 32) s += m2[(size_t)g * H2 + c] * w3[c];
#pragma unroll
    for (int off = 16; off > 0; off >>= 1) s += __shfl_xor_sync(0xFFFFFFFFu, s, off);
    if (lane == 0) out[g] = s + b3[0];
}

// ---------------- launch ------------------------------------------------------
extern "C" void kernel_launch(void* const* d_in, const int* in_sizes, int n_in,
                              void* d_out, int out_size) {
    const int* x_feat     = (const int*)d_in[0];
    const int* edge_index = (const int*)d_in[1];
    const int* eaf        = (const int*)d_in[2];
    const int* batch      = (const int*)d_in[3];
    const float* rdkit    = (const float*)d_in[4];
    const float* atom_emb = (const float*)d_in[5];
    const float* bond_emb = (const float*)d_in[6];
    const float* c1w1 = (const float*)d_in[7];
    const float* c1b1 = (const float*)d_in[8];
    const float* c1w2 = (const float*)d_in[9];
    const float* c1b2 = (const float*)d_in[10];
    const float* c2w1 = (const float*)d_in[11];
    const float* c2b1 = (const float*)d_in[12];
    const float* c2w2 = (const float*)d_in[13];
    const float* c2b2 = (const float*)d_in[14];
    const float* mw1 = (const float*)d_in[15];
    const float* mb1 = (const float*)d_in[16];
    const float* mw2 = (const float*)d_in[17];
    const float* mb2 = (const float*)d_in[18];
    const float* mw3 = (const float*)d_in[19];
    const float* mb3 = (const float*)d_in[20];
    float* out = (float*)d_out;

    const int N = in_sizes[0] / 9;
    const int E = in_sizes[1] / 2;
    const int G = in_sizes[4] / RDM;

    float *p_x0, *p_agg, *p_x1, *p_x2, *p_min, *p_m1, *p_m2;
    uint4* p_wp;
    cudaGetSymbolAddress((void**)&p_x0, g_x0);
    cudaGetSymbolAddress((void**)&p_agg, g_agg);
    cudaGetSymbolAddress((void**)&p_x1, g_x1);
    cudaGetSymbolAddress((void**)&p_x2, g_x2);
    cudaGetSymbolAddress((void**)&p_min, g_min);
    cudaGetSymbolAddress((void**)&p_m1, g_m1);
    cudaGetSymbolAddress((void**)&p_m2, g_m2);
    cudaGetSymbolAddress((void**)&p_wp, g_wp);

    cudaFuncSetAttribute(gemm_fused_kernel,
                         cudaFuncAttributeMaxDynamicSharedMemorySize, FSM);

    const int agg_blocks = (N + 7) / 8;
    const int ntiles = (N + 127) / 128;
    const int encode_blocks = (N * 32 + 255) / 256;
    const int scan_blocks = (N + 1023) / 1024;

    prep_combo_kernel<<<2304 + ZB + encode_blocks, 256>>>(                    // 1
        x_feat, atom_emb, bond_emb, c1w1, c1w2, c2w1, c2w2, p_x0, N);
    edge_prep_kernel<<<(E + 255) / 256, 256>>>(edge_index, eaf, E);           // 2
    scan1_kernel<<<scan_blocks, 1024>>>(N);                                   // 3
    scan23_kernel<<<scan_blocks, 1024>>>(N, E, scan_blocks);                  // 4
    scatter_kernel<<<(E + 255) / 256, 256>>>(edge_index, E);                  // 5

    // ---- conv1 ----
    agg_gather_kernel<<<agg_blocks, 256>>>(p_x0, p_agg, N);                   // 6
    gemm_fused_kernel<<<GEMM_GRID, 256, FSM>>>(p_agg, p_wp + 0 * 4096, p_wp + 1 * 4096,
                                               c1b1, c1b2, p_x1, N, ntiles);

    // ---- conv2 ----
    agg_gather_kernel<<<agg_blocks, 256>>>(p_x1, p_agg, N);
    gemm_fused_kernel<<<GEMM_GRID, 256, FSM>>>(p_agg, p_wp + 2 * 4096, p_wp + 3 * 4096,
                                               c2b1, c2b2, p_x2, N, ntiles);

    // ---- fused pool + concat (no atomics, no memset) ----
    pool_concat_kernel<<<G, 128>>>(p_x2, batch, rdkit, p_min, N);

    // ---- MLP (fp32 SIMT; small) ----
    gemm_kernel<64, 64, 8, 4, 8, true, 1><<<dim3(G / 64, H1 / 64), 128>>>(
        p_min, mw1, mb1, p_m1, G, KMLP1, H1);
    gemm_kernel<64, 64, 8, 4, 8, true, 1><<<dim3(G / 64, H2 / 64), 128>>>(
        p_m1, mw2, mb2, p_m2, G, H1, H2);
    final_dot_kernel<<<(G * 32 + 255) / 256, 256>>>(p_m2, mw3, mb3, out, G);

    (void)n_in; (void)out_size;
}

// round 17
// speedup vs baseline: 1.3438x; 1.0463x over previous
#include <cuda_runtime.h>
#include <cuda_fp16.h>
#include <cstdint>

// Problem constants (fixed by the dataset)
#define ND 128
#define NMAX 50000
#define EMAX 640000
#define GMAX 1024
#define RDM 200
#define H1 512
#define H2 256
#define KMLP1 (ND + RDM)   // 328

// ---------------- scratch (device globals; no allocation allowed) ----------
__device__ float g_x0[NMAX * ND];
__device__ float g_agg[NMAX * ND];
__device__ float g_x1[NMAX * ND];
__device__ float g_x2[NMAX * ND];
__device__ float g_min[GMAX * KMLP1];
__device__ float g_m1[GMAX * H1];
__device__ float g_m2[GMAX * H2];
// prepped conv weights: per matrix 64KB = Wt hi (32KB) + Wt lo (32KB), [n][k] fp16
__device__ uint4 g_wp[4][4096];
// combined bond table in fp16: bsum16[code][c] = b0[f0][c]+b1[f1][c]+b2[f2][c]
__device__ __half g_bsum16[4096 * 128];   // 1MB, L2-resident
// CSR sort scratch. g_deg is zero at the START of every execution:
// zero-initialized at module load; re-zeroed by scatter_kernel each run
// (after the scan has consumed it). Deterministic across graph replays.
__device__ int g_deg[NMAX];
__device__ int g_off[NMAX + 1];
__device__ int g_pos[NMAX];
__device__ int g_part[64];
__device__ int g_emeta[EMAX];    // packed per-edge meta (src | f0<<16 | f1<<20 | f2<<24)
__device__ int g_smeta[EMAX];    // meta in dst-sorted order

// ---------------- helpers ----------------------------------------------------
__device__ __forceinline__ unsigned long long pack2(float x, float y) {
    unsigned long long r;
    asm("mov.b64 %0, {%1, %2};" : "=l"(r) : "f"(x), "f"(y));
    return r;
}
__device__ __forceinline__ void unpack2(unsigned long long v, float& x, float& y) {
    asm("mov.b64 {%0, %1}, %2;" : "=f"(x), "=f"(y) : "l"(v));
}
__device__ __forceinline__ void ffma2(unsigned long long& d, unsigned long long a,
                                      unsigned long long b) {
    asm("fma.rn.f32x2 %0, %1, %2, %0;" : "+l"(d) : "l"(a), "l"(b));
}
// hi/lo fp16x2 split of two floats (a=elem0/.x, b=elem1/.y)
__device__ __forceinline__ uint32_t hilo16(float a, float b, uint32_t& lopack) {
    __half2 h2 = __floats2half2_rn(a, b);
    float2 f = __half22float2(h2);
    __half2 l2 = __floats2half2_rn(a - f.x, b - f.y);
    lopack = *reinterpret_cast<uint32_t*>(&l2);
    return *reinterpret_cast<uint32_t*>(&h2);
}
// warp-level fp16 tensor-core mma (baseline PTX, works on plain sm_103)
__device__ __forceinline__ void mma16816(float* c, const uint32_t* a, const uint32_t* b) {
    asm volatile(
        "mma.sync.aligned.m16n8k16.row.col.f32.f16.f16.f32 "
        "{%0,%1,%2,%3}, {%4,%5,%6,%7}, {%8,%9}, {%0,%1,%2,%3};"
        : "+f"(c[0]), "+f"(c[1]), "+f"(c[2]), "+f"(c[3])
        : "r"(a[0]), "r"(a[1]), "r"(a[2]), "r"(a[3]), "r"(b[0]), "r"(b[1]));
}

// ---------------- launch 1: combo — wprep | bsum | edge prep | atom encode ---
// blocks [0,256): W prep; [256,2304): bsum; [2304,2304+EB): edge prep; rest: encode.
// g_deg guaranteed zero at start (see declaration comment).
__global__ void prep_combo_kernel(const int* __restrict__ xf,
                                  const float* __restrict__ aemb,
                                  const float* __restrict__ bemb,
                                  const int* __restrict__ ei,
                                  const int* __restrict__ eaf,
                                  const float* __restrict__ w0, const float* __restrict__ w1,
                                  const float* __restrict__ w2, const float* __restrict__ w3,
                                  float* __restrict__ xout, int N, int E, int EB) {
    if (blockIdx.x < 256) {
        int widx = blockIdx.x >> 6;
        int idx = (blockIdx.x & 63) * 256 + threadIdx.x;   // 0..16383
        const float* W = (widx == 0) ? w0 : (widx == 1) ? w1 : (widx == 2) ? w2 : w3;
        int n = idx >> 7, k = idx & 127;
        float w = W[k * 128 + n];
        __half h = __float2half_rn(w);
        __half l = __float2half_rn(w - __half2float(h));
        __half* base = reinterpret_cast<__half*>(&g_wp[widx][0]);
        base[n * 128 + k] = h;
        base[16384 + n * 128 + k] = l;
        return;
    }
    if (blockIdx.x < 2304) {
        int idx = (blockIdx.x - 256) * 256 + threadIdx.x;   // 0..524287
        int code = idx >> 7, c = idx & 127;
        int f0 = code & 15, f1 = (code >> 4) & 15, f2 = (code >> 8) & 15;
        g_bsum16[idx] = __float2half_rn(bemb[f0 * 128 + c] + bemb[(16 + f1) * 128 + c]
                                        + bemb[(32 + f2) * 128 + c]);
        return;
    }
    if ((int)blockIdx.x < 2304 + EB) {
        int e = (blockIdx.x - 2304) * 256 + threadIdx.x;
        if (e >= E) return;
        int src = ei[e];
        int dst = ei[E + e];
        int f0 = eaf[e * 3 + 0], f1 = eaf[e * 3 + 1], f2 = eaf[e * 3 + 2];
        g_emeta[e] = src | (f0 << 16) | (f1 << 20) | (f2 << 24);
        atomicAdd(&g_deg[dst], 1);
        return;
    }
    // atom encoder (no atomics)
    int warp = ((blockIdx.x - 2304 - EB) * blockDim.x + threadIdx.x) >> 5;
    int lane = threadIdx.x & 31;
    if (warp >= N) return;
    int n = warp;
    float4 acc = make_float4(0.f, 0.f, 0.f, 0.f);
#pragma unroll
    for (int f = 0; f < 9; f++) {
        int id = xf[n * 9 + f];
        const float4* row = reinterpret_cast<const float4*>(aemb + ((f << 6) + id) * ND);
        float4 v = row[lane];
        acc.x += v.x; acc.y += v.y; acc.z += v.z; acc.w += v.w;
    }
    reinterpret_cast<float4*>(xout + (size_t)n * ND)[lane] = acc;
}

// ---------------- launch 2: per-block exclusive scan -------------------------
__global__ void scan1_kernel(int N) {
    __shared__ int sm[1024];
    int i = blockIdx.x * 1024 + threadIdx.x;
    int v = (i < N) ? g_deg[i] : 0;
    sm[threadIdx.x] = v;
    __syncthreads();
#pragma unroll
    for (int ofs = 1; ofs < 1024; ofs <<= 1) {
        int t = (threadIdx.x >= ofs) ? sm[threadIdx.x - ofs] : 0;
        __syncthreads();
        sm[threadIdx.x] += t;
        __syncthreads();
    }
    if (i < N) g_off[i] = sm[threadIdx.x] - v;   // exclusive (block-local)
    if (threadIdx.x == 1023) g_part[blockIdx.x] = sm[1023];
}
// ---------------- launch 3: apply partials (parallel scan of partials) -------
__global__ void scan23_kernel(int N, int E, int nb) {
    __shared__ int sp[64];
    const int tid = threadIdx.x;
    if (tid < 64) sp[tid] = (tid < nb) ? g_part[tid] : 0;
    __syncthreads();
#pragma unroll
    for (int ofs = 1; ofs < 64; ofs <<= 1) {
        int t = (tid >= ofs && tid < 64) ? sp[tid - ofs] : 0;
        __syncthreads();
        if (tid < 64) sp[tid] += t;
        __syncthreads();
    }
    int pref = (blockIdx.x == 0) ? 0 : sp[blockIdx.x - 1];
    int i = blockIdx.x * 1024 + tid;
    if (i < N) {
        int v = g_off[i] + pref;
        g_off[i] = v;
        g_pos[i] = v;
    }
    if (i == 0) g_off[N] = E;
}
// ---------------- launch 4: scatter + re-zero deg ----------------------------
__global__ void scatter_kernel(const int* __restrict__ ei, int E, int N) {
    int e = blockIdx.x * blockDim.x + threadIdx.x;
    if (e < N) g_deg[e] = 0;
    if (e >= E) return;
    int dst = ei[E + e];
    int p = atomicAdd(&g_pos[dst], 1);
    g_smeta[p] = g_emeta[e];
}

// ---------------- launch 5: gather-aggregate ---------------------------------
// out[n] = x[n] + sum relu(x[src] + bsum16[code]); fp16 bond row (1MB L2 table).
__global__ void __launch_bounds__(256)
agg_gather_kernel(const float* __restrict__ xin, float* __restrict__ out, int N) {
    int wid = threadIdx.x >> 5, lane = threadIdx.x & 31;
    int n = blockIdx.x * 8 + wid;
    if (n >= N) return;
    int s = g_off[n], e_end = g_off[n + 1];
    float4 acc = reinterpret_cast<const float4*>(xin + (size_t)n * ND)[lane];
    for (int base = s; base < e_end; base += 32) {
        int cnt = min(32, e_end - base);
        int mb = (lane < cnt) ? g_smeta[base + lane] : 0;
        int i = 0;
#define ACC_EDGE(m, xs)                                                                    \
        {                                                                                  \
            uint2 bu = __ldg(reinterpret_cast<const uint2*>(                               \
                g_bsum16 + (size_t)(((m) >> 16) & 0xFFF) * ND) + lane);                    \
            float2 b01 = __half22float2(*reinterpret_cast<__half2*>(&bu.x));               \
            float2 b23 = __half22float2(*reinterpret_cast<__half2*>(&bu.y));               \
            acc.x += fmaxf((xs).x + b01.x, 0.f);                                           \
            acc.y += fmaxf((xs).y + b01.y, 0.f);                                           \
            acc.z += fmaxf((xs).z + b23.x, 0.f);                                           \
            acc.w += fmaxf((xs).w + b23.y, 0.f);                                           \
        }
        for (; i + 4 <= cnt; i += 4) {
            int m0 = __shfl_sync(0xFFFFFFFFu, mb, i);
            int m1 = __shfl_sync(0xFFFFFFFFu, mb, i + 1);
            int m2 = __shfl_sync(0xFFFFFFFFu, mb, i + 2);
            int m3 = __shfl_sync(0xFFFFFFFFu, mb, i + 3);
            float4 xs0 = reinterpret_cast<const float4*>(xin + (size_t)(m0 & 0xFFFF) * ND)[lane];
            float4 xs1 = reinterpret_cast<const float4*>(xin + (size_t)(m1 & 0xFFFF) * ND)[lane];
            float4 xs2 = reinterpret_cast<const float4*>(xin + (size_t)(m2 & 0xFFFF) * ND)[lane];
            float4 xs3 = reinterpret_cast<const float4*>(xin + (size_t)(m3 & 0xFFFF) * ND)[lane];
            ACC_EDGE(m0, xs0)
            ACC_EDGE(m1, xs1)
            ACC_EDGE(m2, xs2)
            ACC_EDGE(m3, xs3)
        }
        for (; i < cnt; i++) {
            int m = __shfl_sync(0xFFFFFFFFu, mb, i);
            float4 xs = reinterpret_cast<const float4*>(xin + (size_t)(m & 0xFFFF) * ND)[lane];
            ACC_EDGE(m, xs)
        }
#undef ACC_EDGE
    }
    reinterpret_cast<float4*>(out + (size_t)n * ND)[lane] = acc;
}

// ---------------- persistent fused 2-layer tensor-core conv GEMM -------------
// C = relu(A @ W1 + b1) @ W2 + b2; fp16 3-chain (AhiWhi + AloWhi + AhiWlo).
#define SAK 136   // padded fp16 stride (272B rows)
#define TTILE (128 * SAK * 2)      // 34816 B
#define FSM (6 * TTILE)            // Ahi,Alo,W1hi,W1lo,W2hi,W2lo = 208896 B
#define GEMM_GRID 148

__global__ void __launch_bounds__(256, 1)
gemm_fused_kernel(const float* __restrict__ A,
                  const uint4* __restrict__ Wp1, const uint4* __restrict__ Wp2,
                  const float* __restrict__ b1, const float* __restrict__ b2,
                  float* __restrict__ C, int M, int ntiles) {
    extern __shared__ char dsm[];
    __shared__ float s_b1[128];
    __shared__ float s_b2[128];

    char* pAhi  = dsm;
    char* pAlo  = dsm + 1 * TTILE;
    char* pW1hi = dsm + 2 * TTILE;
    char* pW1lo = dsm + 3 * TTILE;
    char* pW2hi = dsm + 4 * TTILE;
    char* pW2lo = dsm + 5 * TTILE;
    const uint32_t* sAhi = (const uint32_t*)pAhi;
    const uint32_t* sAlo = (const uint32_t*)pAlo;

    const int tid = threadIdx.x, wid = tid >> 5, lane = tid & 31;
    const int g = lane >> 2, q = lane & 3;
    const int wm = wid & 3, wn = wid >> 2;

    if (tid < 128) { s_b1[tid] = b1[tid]; s_b2[tid] = b2[tid]; }

    // ---- stage W1, W2 once (hi + lo, 32KB each part) ----
#pragma unroll
    for (int i = 0; i < 8; i++) {
        int u = tid + i * 256;              // 0..2047
        int n = u >> 4, kc = u & 15;
        *(uint4*)(pW1hi + n * (SAK * 2) + kc * 16) = Wp1[u];
        *(uint4*)(pW1lo + n * (SAK * 2) + kc * 16) = Wp1[u + 2048];
        *(uint4*)(pW2hi + n * (SAK * 2) + kc * 16) = Wp2[u];
        *(uint4*)(pW2lo + n * (SAK * 2) + kc * 16) = Wp2[u + 2048];
    }

    const int ra0 = wm * 32 + g;
    const int nb0 = wn * 64 + g;

    for (int t = blockIdx.x; t < ntiles; t += GEMM_GRID) {
        const int brow = t * 128;
        __syncthreads();   // W ready (1st iter) / prior tile's readers done

        // ---- stage A: fp32 -> hi/lo fp16 ----
        {
            int row = tid >> 1;
            int c0 = (tid & 1) * 64;
            bool valid = (brow + row) < M;
            const float4* a4 = (const float4*)(A + (size_t)(brow + row) * 128 + c0);
            char* dAh = pAhi + row * (SAK * 2) + c0 * 2;
            char* dAl = pAlo + row * (SAK * 2) + c0 * 2;
#pragma unroll
            for (int i = 0; i < 8; i++) {
                float4 v0 = make_float4(0.f, 0.f, 0.f, 0.f), v1 = v0;
                if (valid) { v0 = a4[i * 2]; v1 = a4[i * 2 + 1]; }
                uint4 h, l;
                h.x = hilo16(v0.x, v0.y, l.x);
                h.y = hilo16(v0.z, v0.w, l.y);
                h.z = hilo16(v1.x, v1.y, l.z);
                h.w = hilo16(v1.z, v1.w, l.w);
                *(uint4*)(dAh + i * 16) = h;
                *(uint4*)(dAl + i * 16) = l;
            }
        }
        __syncthreads();

        float acc[2][8][4];

        // ================= layer 1 =================
#pragma unroll
        for (int mt = 0; mt < 2; mt++)
#pragma unroll
            for (int nt = 0; nt < 8; nt++)
#pragma unroll
                for (int j = 0; j < 4; j++) acc[mt][nt][j] = 0.f;

        {
            const uint32_t* sWhi = (const uint32_t*)pW1hi;
            const uint32_t* sWlo = (const uint32_t*)pW1lo;
#pragma unroll
            for (int ks = 0; ks < 8; ks++) {
                const int k0 = ks * 16 + q * 2;
                uint32_t ah[2][4], al[2][4];
#pragma unroll
                for (int mt = 0; mt < 2; mt++) {
                    int r = ra0 + mt * 16;
                    int i00 = (r * SAK + k0) >> 1;
                    int i10 = ((r + 8) * SAK + k0) >> 1;
                    ah[mt][0] = sAhi[i00];     ah[mt][1] = sAhi[i10];
                    ah[mt][2] = sAhi[i00 + 4]; ah[mt][3] = sAhi[i10 + 4];
                    al[mt][0] = sAlo[i00];     al[mt][1] = sAlo[i10];
                    al[mt][2] = sAlo[i00 + 4]; al[mt][3] = sAlo[i10 + 4];
                }
#pragma unroll
                for (int nt = 0; nt < 8; nt++) {
                    int n = nb0 + nt * 8;
                    int ib = (n * SAK + k0) >> 1;
                    uint32_t bh[2], bl[2];
                    bh[0] = sWhi[ib]; bh[1] = sWhi[ib + 4];
                    bl[0] = sWlo[ib]; bl[1] = sWlo[ib + 4];
#pragma unroll
                    for (int mt = 0; mt < 2; mt++) {
                        mma16816(acc[mt][nt], ah[mt], bh);
                        mma16816(acc[mt][nt], al[mt], bh);
                        mma16816(acc[mt][nt], ah[mt], bl);
                    }
                }
            }
        }
        __syncthreads();   // everyone done reading A tiles before overwrite

        // ---- h = relu(acc + b1) -> hi/lo fp16 back into A buffers ----
#pragma unroll
        for (int mt = 0; mt < 2; mt++) {
            int r0 = wm * 32 + mt * 16 + g;
#pragma unroll
            for (int nt = 0; nt < 8; nt++) {
                int col = wn * 64 + nt * 8 + q * 2;
                float bx = s_b1[col], by = s_b1[col + 1];
                float x0 = fmaxf(acc[mt][nt][0] + bx, 0.f);
                float y0 = fmaxf(acc[mt][nt][1] + by, 0.f);
                float x1 = fmaxf(acc[mt][nt][2] + bx, 0.f);
                float y1 = fmaxf(acc[mt][nt][3] + by, 0.f);
                uint32_t l0, l1;
                uint32_t h0 = hilo16(x0, y0, l0);
                uint32_t h1 = hilo16(x1, y1, l1);
                uint32_t o0 = (uint32_t)(r0 * SAK + col) * 2u;
                uint32_t o1 = (uint32_t)((r0 + 8) * SAK + col) * 2u;
                *(uint32_t*)(pAhi + o0) = h0;
                *(uint32_t*)(pAlo + o0) = l0;
                *(uint32_t*)(pAhi + o1) = h1;
                *(uint32_t*)(pAlo + o1) = l1;
            }
        }
        __syncthreads();

        // ================= layer 2 =================
#pragma unroll
        for (int mt = 0; mt < 2; mt++)
#pragma unroll
            for (int nt = 0; nt < 8; nt++)
#pragma unroll
                for (int j = 0; j < 4; j++) acc[mt][nt][j] = 0.f;

        {
            const uint32_t* sWhi = (const uint32_t*)pW2hi;
            const uint32_t* sWlo = (const uint32_t*)pW2lo;
#pragma unroll
            for (int ks = 0; ks < 8; ks++) {
                const int k0 = ks * 16 + q * 2;
                uint32_t ah[2][4], al[2][4];
#pragma unroll
                for (int mt = 0; mt < 2; mt++) {
                    int r = ra0 + mt * 16;
                    int i00 = (r * SAK + k0) >> 1;
                    int i10 = ((r + 8) * SAK + k0) >> 1;
                    ah[mt][0] = sAhi[i00];     ah[mt][1] = sAhi[i10];
                    ah[mt][2] = sAhi[i00 + 4]; ah[mt][3] = sAhi[i10 + 4];
                    al[mt][0] = sAlo[i00];     al[mt][1] = sAlo[i10];
                    al[mt][2] = sAlo[i00 + 4]; al[mt][3] = sAlo[i10 + 4];
                }
#pragma unroll
                for (int nt = 0; nt < 8; nt++) {
                    int n = nb0 + nt * 8;
                    int ib = (n * SAK + k0) >> 1;
                    uint32_t bh[2], bl[2];
                    bh[0] = sWhi[ib]; bh[1] = sWhi[ib + 4];
                    bl[0] = sWlo[ib]; bl[1] = sWlo[ib + 4];
#pragma unroll
                    for (int mt = 0; mt < 2; mt++) {
                        mma16816(acc[mt][nt], ah[mt], bh);
                        mma16816(acc[mt][nt], al[mt], bh);
                        mma16816(acc[mt][nt], ah[mt], bl);
                    }
                }
            }
        }

        // ---- epilogue: C = acc + b2 ----
#pragma unroll
        for (int mt = 0; mt < 2; mt++) {
            int r0 = brow + wm * 32 + mt * 16 + g;
#pragma unroll
            for (int nt = 0; nt < 8; nt++) {
                int col = wn * 64 + nt * 8 + q * 2;
                float bx = s_b2[col], by = s_b2[col + 1];
                if (r0 < M) {
                    float2 o; o.x = acc[mt][nt][0] + bx; o.y = acc[mt][nt][1] + by;
                    *(float2*)(C + (size_t)r0 * 128 + col) = o;
                }
                if (r0 + 8 < M) {
                    float2 o; o.x = acc[mt][nt][2] + bx; o.y = acc[mt][nt][3] + by;
                    *(float2*)(C + (size_t)(r0 + 8) * 128 + col) = o;
                }
            }
        }
    }
}

// ---------------- fused pool + concat: one block per graph -------------------
__global__ void __launch_bounds__(128)
pool_concat_kernel(const float* __restrict__ x, const int* __restrict__ batch,
                   const float* __restrict__ rdkit, float* __restrict__ out, int N) {
    const int gidx = blockIdx.x;
    const int c = threadIdx.x;
    int lo = 0, hi = N;
    while (lo < hi) { int mid = (lo + hi) >> 1; if (batch[mid] < gidx) lo = mid + 1; else hi = mid; }
    int lo2 = lo, hi2 = N;
    while (lo2 < hi2) { int mid = (lo2 + hi2) >> 1; if (batch[mid] <= gidx) lo2 = mid + 1; else hi2 = mid; }
    float s = 0.f;
    for (int r = lo; r < lo2; r++) s += x[(size_t)r * ND + c];
    float cnt = (float)max(lo2 - lo, 1);
    out[(size_t)gidx * KMLP1 + c] = s / cnt;
    for (int j = c; j < RDM; j += 128)
        out[(size_t)gidx * KMLP1 + ND + j] = rdkit[(size_t)gidx * RDM + j];
}

// ---------------- fp32 GEMM (MLP only) --------------------------------------
template <int BM, int BN, int BK, int TM, int TN, bool RELU, int MINB>
__global__ void __launch_bounds__((BM / TM) * (BN / TN), MINB)
gemm_kernel(const float* __restrict__ A,
            const float* __restrict__ W, const float* __restrict__ bias,
            float* __restrict__ C, int M, int K, int Nc) {
    constexpr int THREADS = (BM / TM) * (BN / TN);
    __shared__ float sA[BK][BM + 4];
    __shared__ float sW[BK][BN];

    const int tid = threadIdx.x;
    const int tn = tid % (BN / TN);
    const int tm = tid / (BN / TN);
    const int row0 = tm * TM;
    const int col0 = tn * TN;
    const int brow = blockIdx.x * BM;
    const int bcol = blockIdx.y * BN;

    unsigned long long acc[TM][TN / 2];
#pragma unroll
    for (int i = 0; i < TM; i++)
#pragma unroll
        for (int j = 0; j < TN / 2; j++) acc[i][j] = 0ull;

    for (int k0 = 0; k0 < K; k0 += BK) {
        constexpr int A_LOADS = (BM * BK / 4) / THREADS;
#pragma unroll
        for (int i = 0; i < A_LOADS; i++) {
            int idx = tid + i * THREADS;
            int m = idx / (BK / 4);
            int kq = idx % (BK / 4);
            int grow = brow + m;
            float4 v = make_float4(0.f, 0.f, 0.f, 0.f);
            if (grow < M)
                v = *reinterpret_cast<const float4*>(A + (size_t)grow * K + k0 + kq * 4);
            sA[kq * 4 + 0][m] = v.x;
            sA[kq * 4 + 1][m] = v.y;
            sA[kq * 4 + 2][m] = v.z;
            sA[kq * 4 + 3][m] = v.w;
        }
        constexpr int W_LOADS = (BK * BN / 4) / THREADS;
#pragma unroll
        for (int i = 0; i < W_LOADS; i++) {
            int idx = tid + i * THREADS;
            int kk = idx / (BN / 4);
            int cq = idx % (BN / 4);
            *reinterpret_cast<float4*>(&sW[kk][cq * 4]) =
                *reinterpret_cast<const float4*>(W + (size_t)(k0 + kk) * Nc + bcol + cq * 4);
        }
        __syncthreads();

#pragma unroll
        for (int kk = 0; kk < BK; kk++) {
            float a[TM];
#pragma unroll
            for (int i = 0; i < TM; i += 4) {
                float4 t = *reinterpret_cast<const float4*>(&sA[kk][row0 + i]);
                a[i] = t.x; a[i + 1] = t.y; a[i + 2] = t.z; a[i + 3] = t.w;
            }
            unsigned long long wv[TN / 2];
#pragma unroll
            for (int j = 0; j < TN; j += 4) {
                float4 t = *reinterpret_cast<const float4*>(&sW[kk][col0 + j]);
                wv[j / 2] = pack2(t.x, t.y);
                wv[j / 2 + 1] = pack2(t.z, t.w);
            }
#pragma unroll
            for (int i = 0; i < TM; i++) {
                unsigned long long ad = pack2(a[i], a[i]);
#pragma unroll
                for (int j = 0; j < TN / 2; j++) ffma2(acc[i][j], ad, wv[j]);
            }
        }
        __syncthreads();
    }

    float2 bv[TN / 2];
#pragma unroll
    for (int j = 0; j < TN / 2; j++)
        bv[j] = *reinterpret_cast<const float2*>(bias + bcol + col0 + 2 * j);
#pragma unroll
    for (int i = 0; i < TM; i++) {
        int grow = brow + row0 + i;
        if (grow >= M) continue;
#pragma unroll
        for (int j = 0; j < TN / 2; j++) {
            float x, y;
            unpack2(acc[i][j], x, y);
            x += bv[j].x; y += bv[j].y;
            if (RELU) { x = fmaxf(x, 0.f); y = fmaxf(y, 0.f); }
            float2 o; o.x = x; o.y = y;
            *reinterpret_cast<float2*>(C + (size_t)grow * Nc + bcol + col0 + 2 * j) = o;
        }
    }
}

// ---------------- final layer: [G,256] @ [256,1] -----------------------------
__global__ void final_dot_kernel(const float* __restrict__ m2,
                                 const float* __restrict__ w3,
                                 const float* __restrict__ b3,
                                 float* __restrict__ out, int G) {
    int warp = (blockIdx.x * blockDim.x + threadIdx.x) >> 5;
    int lane = threadIdx.x & 31;
    if (warp >= G) return;
    int g = warp;
    float s = 0.f;
#pragma unroll
    for (int c = lane; c < H2; c += 32) s += m2[(size_t)g * H2 + c] * w3[c];
#pragma unroll
    for (int off = 16; off > 0; off >>= 1) s += __shfl_xor_sync(0xFFFFFFFFu, s, off);
    if (lane == 0) out[g] = s + b3[0];
}

// ---------------- launch ------------------------------------------------------
extern "C" void kernel_launch(void* const* d_in, const int* in_sizes, int n_in,
                              void* d_out, int out_size) {
    const int* x_feat     = (const int*)d_in[0];
    const int* edge_index = (const int*)d_in[1];
    const int* eaf        = (const int*)d_in[2];
    const int* batch      = (const int*)d_in[3];
    const float* rdkit    = (const float*)d_in[4];
    const float* atom_emb = (const float*)d_in[5];
    const float* bond_emb = (const float*)d_in[6];
    const float* c1w1 = (const float*)d_in[7];
    const float* c1b1 = (const float*)d_in[8];
    const float* c1w2 = (const float*)d_in[9];
    const float* c1b2 = (const float*)d_in[10];
    const float* c2w1 = (const float*)d_in[11];
    const float* c2b1 = (const float*)d_in[12];
    const float* c2w2 = (const float*)d_in[13];
    const float* c2b2 = (const float*)d_in[14];
    const float* mw1 = (const float*)d_in[15];
    const float* mb1 = (const float*)d_in[16];
    const float* mw2 = (const float*)d_in[17];
    const float* mb2 = (const float*)d_in[18];
    const float* mw3 = (const float*)d_in[19];
    const float* mb3 = (const float*)d_in[20];
    float* out = (float*)d_out;

    const int N = in_sizes[0] / 9;
    const int E = in_sizes[1] / 2;
    const int G = in_sizes[4] / RDM;

    float *p_x0, *p_agg, *p_x1, *p_x2, *p_min, *p_m1, *p_m2;
    uint4* p_wp;
    cudaGetSymbolAddress((void**)&p_x0, g_x0);
    cudaGetSymbolAddress((void**)&p_agg, g_agg);
    cudaGetSymbolAddress((void**)&p_x1, g_x1);
    cudaGetSymbolAddress((void**)&p_x2, g_x2);
    cudaGetSymbolAddress((void**)&p_min, g_min);
    cudaGetSymbolAddress((void**)&p_m1, g_m1);
    cudaGetSymbolAddress((void**)&p_m2, g_m2);
    cudaGetSymbolAddress((void**)&p_wp, g_wp);

    cudaFuncSetAttribute(gemm_fused_kernel,
                         cudaFuncAttributeMaxDynamicSharedMemorySize, FSM);

    const int agg_blocks = (N + 7) / 8;
    const int ntiles = (N + 127) / 128;
    const int encode_blocks = (N * 32 + 255) / 256;
    const int scan_blocks = (N + 1023) / 1024;
    const int EB = (E + 255) / 256;

    prep_combo_kernel<<<2304 + EB + encode_blocks, 256>>>(                    // 1
        x_feat, atom_emb, bond_emb, edge_index, eaf,
        c1w1, c1w2, c2w1, c2w2, p_x0, N, E, EB);
    scan1_kernel<<<scan_blocks, 1024>>>(N);                                   // 2
    scan23_kernel<<<scan_blocks, 1024>>>(N, E, scan_blocks);                  // 3
    scatter_kernel<<<(max(E, N) + 255) / 256, 256>>>(edge_index, E, N);       // 4

    // ---- conv1 ----
    agg_gather_kernel<<<agg_blocks, 256>>>(p_x0, p_agg, N);                   // 5
    gemm_fused_kernel<<<GEMM_GRID, 256, FSM>>>(p_agg, p_wp + 0 * 4096, p_wp + 1 * 4096,
                                               c1b1, c1b2, p_x1, N, ntiles);

    // ---- conv2 ----
    agg_gather_kernel<<<agg_blocks, 256>>>(p_x1, p_agg, N);
    gemm_fused_kernel<<<GEMM_GRID, 256, FSM>>>(p_agg, p_wp + 2 * 4096, p_wp + 3 * 4096,
                                               c2b1, c2b2, p_x2, N, ntiles);

    // ---- fused pool + concat ----
    pool_concat_kernel<<<G, 128>>>(p_x2, batch, rdkit, p_min, N);

    // ---- MLP (fp32 SIMT; small) ----
    gemm_kernel<64, 64, 8, 4, 8, true, 1><<<dim3(G / 64, H1 / 64), 128>>>(
        p_min, mw1, mb1, p_m1, G, KMLP1, H1);
    gemm_kernel<64, 64, 8, 4, 8, true, 1><<<dim3(G / 64, H2 / 64), 128>>>(
        p_m1, mw2, mb2, p_m2, G, H1, H2);
    final_dot_kernel<<<(G * 32 + 255) / 256, 256>>>(p_m2, mw3, mb3, out, G);

    (void)n_in; (void)out_size;
}